// round 5
// baseline (speedup 1.0000x reference)
#include <cuda_runtime.h>
#include <cstdint>

#define B_   8
#define S_   1024
#define HID_ 1024
#define NH_  16
#define HD_  64

// ---------------- scratch (no allocations allowed) ----------------
__device__ float g_q[B_ * NH_ * S_ * HD_];   // [b,h,s,d], pre-scaled 1/8, +q_bias
__device__ float g_k[B_ * NH_ * S_ * HD_];
__device__ float g_v[B_ * NH_ * S_ * HD_];
__device__ float g_ctx[B_ * S_ * HID_];      // [b,s,h,d]
__device__ float g_h[B_ * S_ * HID_];

// ---------------- helpers ----------------
__device__ __forceinline__ uint32_t smem_u32(const void* p) {
    return (uint32_t)__cvta_generic_to_shared(p);
}
__device__ __forceinline__ void cp16(uint32_t s, const void* g) {
    asm volatile("cp.async.cg.shared.global [%0], [%1], 16;\n" :: "r"(s), "l"(g));
}
__device__ __forceinline__ void cp_commit() { asm volatile("cp.async.commit_group;\n"); }
template<int N> __device__ __forceinline__ void cp_wait() {
    asm volatile("cp.async.wait_group %0;\n" :: "n"(N));
}
__device__ __forceinline__ void mma_tf32(float c[4],
    uint32_t a0, uint32_t a1, uint32_t a2, uint32_t a3, uint32_t b0, uint32_t b1)
{
    asm volatile(
        "mma.sync.aligned.m16n8k8.row.col.f32.tf32.tf32.f32 "
        "{%0,%1,%2,%3},{%4,%5,%6,%7},{%8,%9},{%0,%1,%2,%3};\n"
        : "+f"(c[0]), "+f"(c[1]), "+f"(c[2]), "+f"(c[3])
        : "r"(a0), "r"(a1), "r"(a2), "r"(a3), "r"(b0), "r"(b1));
}

// load 128 rows x 16 floats tile into smem [row*20 + col] via cp.async
__device__ __forceinline__ void cpa_tile128x16(float* dst, const float* src, int ld) {
    const int tid = threadIdx.x;
    const int row = tid >> 2;
    const int c4  = (tid & 3) * 4;
    cp16(smem_u32(dst + row * 20 + c4),        src + (size_t)row * ld + c4);
    cp16(smem_u32(dst + (row + 64) * 20 + c4), src + (size_t)(row + 64) * ld + c4);
}

// load 128 rows x 64 floats into smem [row*68 + col] via cp.async (8 cp16/thread)
__device__ __forceinline__ void cpa_tile128x64(float* dst, const float* src) {
    const int tid = threadIdx.x;
#pragma unroll
    for (int i = 0; i < 8; i++) {
        int idx = tid + i * 256;
        int r = idx >> 4, c = (idx & 15) * 4;
        cp16(smem_u32(dst + r * 68 + c), src + (size_t)r * HD_ + c);
    }
}

// 128x128 block-tile compute on one BK=16 chunk (8 warps: 2m x 4n, warp tile 64x32)
__device__ __forceinline__ void mma_block_128x128(
    const float* As, const float* Bs,
    int warp_m, int warp_n, int gid, int tig, float acc[4][4][4])
{
#pragma unroll
    for (int ks = 0; ks < 16; ks += 8) {
        uint32_t a[4][4], b[4][2];
#pragma unroll
        for (int i = 0; i < 4; i++) {
            int r = warp_m * 64 + i * 16 + gid;
            a[i][0] = __float_as_uint(As[r * 20 + ks + tig]);
            a[i][1] = __float_as_uint(As[(r + 8) * 20 + ks + tig]);
            a[i][2] = __float_as_uint(As[r * 20 + ks + tig + 4]);
            a[i][3] = __float_as_uint(As[(r + 8) * 20 + ks + tig + 4]);
        }
#pragma unroll
        for (int j = 0; j < 4; j++) {
            int n = warp_n * 32 + j * 8 + gid;
            b[j][0] = __float_as_uint(Bs[n * 20 + ks + tig]);
            b[j][1] = __float_as_uint(Bs[n * 20 + ks + tig + 4]);
        }
#pragma unroll
        for (int i = 0; i < 4; i++)
#pragma unroll
            for (int j = 0; j < 4; j++)
                mma_tf32(acc[i][j], a[i][0], a[i][1], a[i][2], a[i][3], b[j][0], b[j][1]);
    }
}

// =================================================================
// K1: QKV projection. C[m,n] = X[m,:] . W[n,:], M=8192, N=3072, K=1024
// =================================================================
__device__ __forceinline__ void qkv_store(int bb, int ss, int n, float2 v,
                                          const float* qb, const float* vb)
{
    if (n < HID_) {
        float2 o;
        o.x = (v.x + qb[n]) * 0.125f;
        o.y = (v.y + qb[n + 1]) * 0.125f;
        int h = n >> 6, d = n & 63;
        *(float2*)&g_q[(((size_t)(bb * NH_ + h)) * S_ + ss) * HD_ + d] = o;
    } else if (n < 2 * HID_) {
        int nn = n - HID_;
        int h = nn >> 6, d = nn & 63;
        *(float2*)&g_k[(((size_t)(bb * NH_ + h)) * S_ + ss) * HD_ + d] = v;
    } else {
        int nn = n - 2 * HID_;
        float2 o;
        o.x = v.x + vb[nn];
        o.y = v.y + vb[nn + 1];
        int h = nn >> 6, d = nn & 63;
        *(float2*)&g_v[(((size_t)(bb * NH_ + h)) * S_ + ss) * HD_ + d] = o;
    }
}

__global__ void __launch_bounds__(256) qkv_gemm_kernel(
    const float* __restrict__ X, const float* __restrict__ W,
    const float* __restrict__ qb, const float* __restrict__ vb)
{
    __shared__ float As[2][128 * 20];
    __shared__ float Bs[2][128 * 20];
    const int bm = blockIdx.y * 128, bn = blockIdx.x * 128;
    const int tid = threadIdx.x, wid = tid >> 5, lane = tid & 31;
    const int gid = lane >> 2, tig = lane & 3;
    const int warp_m = wid >> 2, warp_n = wid & 3;

    float acc[4][4][4];
#pragma unroll
    for (int i = 0; i < 4; i++)
#pragma unroll
        for (int j = 0; j < 4; j++)
#pragma unroll
            for (int k = 0; k < 4; k++) acc[i][j][k] = 0.f;

    const float* Abase = X + (size_t)bm * HID_;
    const float* Bbase = W + (size_t)bn * HID_;

    cpa_tile128x16(As[0], Abase, HID_);
    cpa_tile128x16(Bs[0], Bbase, HID_);
    cp_commit();

    const int NC = HID_ / 16;
    for (int c = 0; c < NC; c++) {
        int cur = c & 1;
        if (c + 1 < NC) {
            cpa_tile128x16(As[cur ^ 1], Abase + (c + 1) * 16, HID_);
            cpa_tile128x16(Bs[cur ^ 1], Bbase + (c + 1) * 16, HID_);
            cp_commit();
            cp_wait<1>();
        } else {
            cp_wait<0>();
        }
        __syncthreads();
        mma_block_128x128(As[cur], Bs[cur], warp_m, warp_n, gid, tig, acc);
        __syncthreads();
    }

    const int bb = bm >> 10, ss0 = bm & 1023;
#pragma unroll
    for (int i = 0; i < 4; i++) {
        int r = warp_m * 64 + i * 16 + gid;
#pragma unroll
        for (int j = 0; j < 4; j++) {
            int n = bn + warp_n * 32 + j * 8 + tig * 2;
            qkv_store(bb, ss0 + r,     n, make_float2(acc[i][j][0], acc[i][j][1]), qb, vb);
            qkv_store(bb, ss0 + r + 8, n, make_float2(acc[i][j][2], acc[i][j][3]), qb, vb);
        }
    }
}

// =================================================================
// K2 (FUSED): flash attention with rel-pos biases.
// CTA = (b = blockIdx.x, qt = blockIdx.y, h = blockIdx.z), 128 q-rows.
// Loops over 8 K/V tiles of 128; online softmax; ctx accumulated in regs.
// =================================================================
#define VS_STRIDE 132
#define FUSED_SMEM (128*68*4 /*Qs*/ + 2*128*68*4 /*Ks*/ + 64*VS_STRIDE*4 /*Vs*/ + 512 /*mask*/)

extern __shared__ float dynsmem[];

__global__ void __launch_bounds__(256, 1) fused_attn_kernel(
    const float* __restrict__ rel_pos, const float* __restrict__ rel2d,
    const unsigned char* __restrict__ mask)
{
    const int b  = blockIdx.x;
    const int qt = blockIdx.y;
    const int h  = blockIdx.z;
    const int bh = b * NH_ + h;

    float* Qs = dynsmem;                       // [128][68]
    float* Ks = Qs + 128 * 68;                 // 2 x [128][68]
    float* Vs = Ks + 2 * 128 * 68;             // [64][VS_STRIDE]
    float* smaskf = Vs + 64 * VS_STRIDE;       // [128]

    const int tid = threadIdx.x, wid = tid >> 5, lane = tid & 31;
    const int gid = lane >> 2, tig = lane & 3;
    const int kb = tid >> 6;                   // 0..3 (V load)
    const int dd = tid & 63;                   // 0..63 (V load)

    const float* Qg = g_q + (size_t)bh * S_ * HD_ + (size_t)(qt * 128) * HD_;
    const float* Kg = g_k + (size_t)bh * S_ * HD_;
    const float* Vg = g_v + (size_t)bh * S_ * HD_;

    // prologue: Q tile, first K tile
    cpa_tile128x64(Qs, Qg);
    cp_commit();
    cpa_tile128x64(Ks, Kg);
    cp_commit();
    cp_wait<1>();       // Qs ready
    __syncthreads();

    // preload Q fragments (warp owns rows wid*16 .. wid*16+15)
    const int r0 = wid * 16 + gid;
    uint32_t qa[8][4];
#pragma unroll
    for (int kk = 0; kk < 8; kk++) {
        qa[kk][0] = __float_as_uint(Qs[r0 * 68 + kk * 8 + tig]);
        qa[kk][1] = __float_as_uint(Qs[(r0 + 8) * 68 + kk * 8 + tig]);
        qa[kk][2] = __float_as_uint(Qs[r0 * 68 + kk * 8 + tig + 4]);
        qa[kk][3] = __float_as_uint(Qs[(r0 + 8) * 68 + kk * 8 + tig + 4]);
    }

    // online softmax state (rows ra = qt*128+r0, rb = ra+8)
    float m_a = -1e30f, m_b = -1e30f;
    float l_a = 0.f,    l_b = 0.f;
    float cacc[8][4];
#pragma unroll
    for (int jj = 0; jj < 8; jj++)
#pragma unroll
        for (int k = 0; k < 4; k++) cacc[jj][k] = 0.f;

    const int ra = qt * 128 + r0;
    const float* rpA = rel_pos + ((size_t)h * S_ + ra) * S_;
    const float* rpB = rel_pos + ((size_t)h * S_ + ra + 8) * S_;
    const float* r2A = rel2d   + ((size_t)h * S_ + ra) * S_;
    const float* r2B = rel2d   + ((size_t)h * S_ + ra + 8) * S_;
    const unsigned char* mrow = mask + b * S_;

    for (int kt = 0; kt < 8; kt++) {
        const int cur = kt & 1;
        if (kt + 1 < 8) {
            cpa_tile128x64(Ks + (cur ^ 1) * 128 * 68, Kg + (size_t)(kt + 1) * 128 * HD_);
            cp_commit();
        }
        // V wave 1 LDG (overlaps S-MMA)
        float vr[16];
#pragma unroll
        for (int it = 0; it < 16; it++)
            vr[it] = Vg[(size_t)(kt * 128 + it * 4 + kb) * HD_ + dd];
        // mask tile to smem
        if (tid < 128) smaskf[tid] = mrow[kt * 128 + tid] ? -1e30f : 0.f;

        if (kt + 1 < 8) cp_wait<1>(); else cp_wait<0>();
        __syncthreads();   // Ks[cur] ready; prev iter fully done (Vs reusable)

        // ---- S-tile = Q . K^T : warp computes 16 x 128, 16 j-tiles ----
        const float* Kp = Ks + cur * 128 * 68;
        float s[16][4];
#pragma unroll
        for (int j = 0; j < 16; j++)
#pragma unroll
            for (int k = 0; k < 4; k++) s[j][k] = 0.f;
#pragma unroll
        for (int kk = 0; kk < 8; kk++) {
#pragma unroll
            for (int j = 0; j < 16; j++) {
                int n = j * 8 + gid;
                uint32_t b0 = __float_as_uint(Kp[n * 68 + kk * 8 + tig]);
                uint32_t b1 = __float_as_uint(Kp[n * 68 + kk * 8 + tig + 4]);
                mma_tf32(s[j], qa[kk][0], qa[kk][1], qa[kk][2], qa[kk][3], b0, b1);
            }
        }

        // ---- epilogue: + rel_pos + rel_2d + mask; track tile row max ----
        float mxa = -1e30f, mxb = -1e30f;
        const size_t coff = (size_t)kt * 128;
#pragma unroll
        for (int jg = 0; jg < 4; jg++) {
            float2 pa[4], qa2[4], pb[4], qb2[4];
#pragma unroll
            for (int jj = 0; jj < 4; jj++) {
                int n = (jg * 4 + jj) * 8 + tig * 2;
                pa[jj]  = *(const float2*)&rpA[coff + n];
                qa2[jj] = *(const float2*)&r2A[coff + n];
                pb[jj]  = *(const float2*)&rpB[coff + n];
                qb2[jj] = *(const float2*)&r2B[coff + n];
            }
#pragma unroll
            for (int jj = 0; jj < 4; jj++) {
                int j = jg * 4 + jj;
                int n = j * 8 + tig * 2;
                float m0 = smaskf[n], m1 = smaskf[n + 1];
                s[j][0] += pa[jj].x + qa2[jj].x + m0;
                s[j][1] += pa[jj].y + qa2[jj].y + m1;
                s[j][2] += pb[jj].x + qb2[jj].x + m0;
                s[j][3] += pb[jj].y + qb2[jj].y + m1;
                mxa = fmaxf(mxa, fmaxf(s[j][0], s[j][1]));
                mxb = fmaxf(mxb, fmaxf(s[j][2], s[j][3]));
            }
        }
        // reduce max over the 4 lanes holding this row
        mxa = fmaxf(mxa, __shfl_xor_sync(0xffffffffu, mxa, 1));
        mxa = fmaxf(mxa, __shfl_xor_sync(0xffffffffu, mxa, 2));
        mxb = fmaxf(mxb, __shfl_xor_sync(0xffffffffu, mxb, 1));
        mxb = fmaxf(mxb, __shfl_xor_sync(0xffffffffu, mxb, 2));

        float mna = fmaxf(m_a, mxa), mnb = fmaxf(m_b, mxb);
        float sca = __expf(m_a - mna), scb = __expf(m_b - mnb);
        m_a = mna; m_b = mnb;

        float suma = 0.f, sumb = 0.f;
#pragma unroll
        for (int j = 0; j < 16; j++) {
            s[j][0] = __expf(s[j][0] - m_a);
            s[j][1] = __expf(s[j][1] - m_a);
            s[j][2] = __expf(s[j][2] - m_b);
            s[j][3] = __expf(s[j][3] - m_b);
            suma += s[j][0] + s[j][1];
            sumb += s[j][2] + s[j][3];
        }
        l_a = l_a * sca + suma;
        l_b = l_b * scb + sumb;
#pragma unroll
        for (int jj = 0; jj < 8; jj++) {
            cacc[jj][0] *= sca; cacc[jj][1] *= sca;
            cacc[jj][2] *= scb; cacc[jj][3] *= scb;
        }

        // ---- V transpose to smem: Vs[d][k] ----
#pragma unroll
        for (int it = 0; it < 16; it++)
            Vs[dd * VS_STRIDE + it * 4 + kb] = vr[it];
#pragma unroll
        for (int it = 0; it < 16; it++)
            vr[it] = Vg[(size_t)(kt * 128 + (it + 16) * 4 + kb) * HD_ + dd];
#pragma unroll
        for (int it = 0; it < 16; it++)
            Vs[dd * VS_STRIDE + (it + 16) * 4 + kb] = vr[it];
        __syncthreads();   // Vs ready

        // ---- ctx += P . V : 16 k-chunks, P frags from s[] via shuffles ----
        const int base = lane & ~3;
        const int src_lo = base + (tig >> 1);
        const int src_hi = src_lo + 2;
        const bool odd = (tig & 1);
#pragma unroll
        for (int j = 0; j < 16; j++) {
            float t0 = __shfl_sync(0xffffffffu, s[j][0], src_lo);
            float t1 = __shfl_sync(0xffffffffu, s[j][1], src_lo);
            float u0 = __shfl_sync(0xffffffffu, s[j][0], src_hi);
            float u1 = __shfl_sync(0xffffffffu, s[j][1], src_hi);
            float v0 = __shfl_sync(0xffffffffu, s[j][2], src_lo);
            float v1 = __shfl_sync(0xffffffffu, s[j][3], src_lo);
            float w0 = __shfl_sync(0xffffffffu, s[j][2], src_hi);
            float w1 = __shfl_sync(0xffffffffu, s[j][3], src_hi);
            uint32_t a0 = __float_as_uint(odd ? t1 : t0);
            uint32_t a2 = __float_as_uint(odd ? u1 : u0);
            uint32_t a1 = __float_as_uint(odd ? v1 : v0);
            uint32_t a3 = __float_as_uint(odd ? w1 : w0);
#pragma unroll
            for (int jj = 0; jj < 8; jj++) {
                int d = jj * 8 + gid;
                uint32_t b0 = __float_as_uint(Vs[d * VS_STRIDE + j * 8 + tig]);
                uint32_t b1 = __float_as_uint(Vs[d * VS_STRIDE + j * 8 + tig + 4]);
                mma_tf32(cacc[jj], a0, a1, a2, a3, b0, b1);
            }
        }
    }

    // final: reduce l across 4 lanes, normalize, write ctx [b,s,h,d]
    l_a += __shfl_xor_sync(0xffffffffu, l_a, 1);
    l_a += __shfl_xor_sync(0xffffffffu, l_a, 2);
    l_b += __shfl_xor_sync(0xffffffffu, l_b, 1);
    l_b += __shfl_xor_sync(0xffffffffu, l_b, 2);
    float inva = 1.0f / l_a, invb = 1.0f / l_b;

    const size_t obase_a = (((size_t)b * S_ + ra) * NH_ + h) * HD_;
    const size_t obase_b = (((size_t)b * S_ + ra + 8) * NH_ + h) * HD_;
#pragma unroll
    for (int jj = 0; jj < 8; jj++) {
        int d = jj * 8 + tig * 2;
        *(float2*)&g_ctx[obase_a + d] =
            make_float2(cacc[jj][0] * inva, cacc[jj][1] * inva);
        *(float2*)&g_ctx[obase_b + d] =
            make_float2(cacc[jj][2] * invb, cacc[jj][3] * invb);
    }
}

// =================================================================
// K3: out projection + bias + residual. M=8192, N=1024, K=1024
// =================================================================
__global__ void __launch_bounds__(256) outproj_kernel(
    const float* __restrict__ Wout, const float* __restrict__ b_out,
    const float* __restrict__ X)
{
    __shared__ float As[2][128 * 20];
    __shared__ float Bs[2][128 * 20];
    const int bm = blockIdx.y * 128, bn = blockIdx.x * 128;
    const int tid = threadIdx.x, wid = tid >> 5, lane = tid & 31;
    const int gid = lane >> 2, tig = lane & 3;
    const int warp_m = wid >> 2, warp_n = wid & 3;

    float acc[4][4][4];
#pragma unroll
    for (int i = 0; i < 4; i++)
#pragma unroll
        for (int j = 0; j < 4; j++)
#pragma unroll
            for (int k = 0; k < 4; k++) acc[i][j][k] = 0.f;

    const float* Abase = g_ctx + (size_t)bm * HID_;
    const float* Bbase = Wout + (size_t)bn * HID_;

    cpa_tile128x16(As[0], Abase, HID_);
    cpa_tile128x16(Bs[0], Bbase, HID_);
    cp_commit();

    const int NC = HID_ / 16;
    for (int c = 0; c < NC; c++) {
        int cur = c & 1;
        if (c + 1 < NC) {
            cpa_tile128x16(As[cur ^ 1], Abase + (c + 1) * 16, HID_);
            cpa_tile128x16(Bs[cur ^ 1], Bbase + (c + 1) * 16, HID_);
            cp_commit();
            cp_wait<1>();
        } else {
            cp_wait<0>();
        }
        __syncthreads();
        mma_block_128x128(As[cur], Bs[cur], warp_m, warp_n, gid, tig, acc);
        __syncthreads();
    }

#pragma unroll
    for (int i = 0; i < 4; i++) {
        int r0 = bm + warp_m * 64 + i * 16 + gid;
#pragma unroll
        for (int j = 0; j < 4; j++) {
            int n = bn + warp_n * 32 + j * 8 + tig * 2;
            float2 x0 = *(const float2*)&X[(size_t)r0 * HID_ + n];
            float2 x1 = *(const float2*)&X[(size_t)(r0 + 8) * HID_ + n];
            float b0 = b_out[n], b1 = b_out[n + 1];
            *(float2*)&g_h[(size_t)r0 * HID_ + n] =
                make_float2(acc[i][j][0] + b0 + x0.x, acc[i][j][1] + b1 + x0.y);
            *(float2*)&g_h[(size_t)(r0 + 8) * HID_ + n] =
                make_float2(acc[i][j][2] + b0 + x1.x, acc[i][j][3] + b1 + x1.y);
        }
    }
}

// =================================================================
// K4: LayerNorm per row of g_h -> d_out
// =================================================================
__global__ void __launch_bounds__(256) layernorm_kernel(
    const float* __restrict__ gamma, const float* __restrict__ beta,
    float* __restrict__ out)
{
    const size_t row = blockIdx.x;
    const float* hp = g_h + row * HID_;
    const int tid = threadIdx.x;
    const int n = tid * 4;

    float4 v = *(const float4*)(hp + n);
    __shared__ float red[256];

    red[tid] = v.x + v.y + v.z + v.w;
    __syncthreads();
    for (int s = 128; s > 0; s >>= 1) {
        if (tid < s) red[tid] += red[tid + s];
        __syncthreads();
    }
    float mean = red[0] * (1.0f / HID_);
    __syncthreads();

    float dx = v.x - mean, dy = v.y - mean, dz = v.z - mean, dw = v.w - mean;
    red[tid] = dx * dx + dy * dy + dz * dz + dw * dw;
    __syncthreads();
    for (int s = 128; s > 0; s >>= 1) {
        if (tid < s) red[tid] += red[tid + s];
        __syncthreads();
    }
    float inv = rsqrtf(red[0] * (1.0f / HID_) + 1e-12f);

    float4 o;
    o.x = dx * inv * gamma[n + 0] + beta[n + 0];
    o.y = dy * inv * gamma[n + 1] + beta[n + 1];
    o.z = dz * inv * gamma[n + 2] + beta[n + 2];
    o.w = dw * inv * gamma[n + 3] + beta[n + 3];
    *(float4*)(out + row * HID_ + n) = o;
}

// =================================================================
extern "C" void kernel_launch(void* const* d_in, const int* in_sizes, int n_in,
                              void* d_out, int out_size)
{
    const float*         x       = (const float*)d_in[0];
    const unsigned char* mask    = (const unsigned char*)d_in[1];
    const float*         rel_pos = (const float*)d_in[2];
    const float*         rel2d   = (const float*)d_in[3];
    const float*         w_qkv   = (const float*)d_in[4];
    const float*         q_bias  = (const float*)d_in[5];
    const float*         v_bias  = (const float*)d_in[6];
    const float*         w_out   = (const float*)d_in[7];
    const float*         b_out   = (const float*)d_in[8];
    const float*         gamma   = (const float*)d_in[9];
    const float*         beta    = (const float*)d_in[10];
    float*               out     = (float*)d_out;

    static bool attr_set = false;
    // setting the same attribute every call is deterministic & idempotent
    cudaFuncSetAttribute(fused_attn_kernel,
                         cudaFuncAttributeMaxDynamicSharedMemorySize, FUSED_SMEM);
    (void)attr_set;

    qkv_gemm_kernel<<<dim3(24, 64), 256>>>(x, w_qkv, q_bias, v_bias);
    fused_attn_kernel<<<dim3(B_, 8, NH_), 256, FUSED_SMEM>>>(rel_pos, rel2d, mask);
    outproj_kernel<<<dim3(8, 64), 256>>>(w_out, b_out, x);
    layernorm_kernel<<<dim3(B_ * S_), 256>>>(gamma, beta, out);
}

// round 6
// speedup vs baseline: 1.2383x; 1.2383x over previous
#include <cuda_runtime.h>
#include <cuda_bf16.h>
#include <cstdint>

#define B_   8
#define S_   1024
#define HID_ 1024
#define NH_  16
#define HD_  64

// ---------------- scratch (no allocations allowed) ----------------
__device__ __nv_bfloat16 g_q[B_ * NH_ * S_ * HD_];   // [b,h,s,d], pre-scaled 1/8, +q_bias
__device__ __nv_bfloat16 g_k[B_ * NH_ * S_ * HD_];
__device__ __nv_bfloat16 g_v[B_ * NH_ * S_ * HD_];
__device__ float g_bias[(size_t)NH_ * S_ * S_];      // rel_pos + rel_2d (64 MB)
__device__ float g_ctx[B_ * S_ * HID_];              // [b,s,h,d]
__device__ float g_h[B_ * S_ * HID_];

// ---------------- helpers ----------------
__device__ __forceinline__ uint32_t smem_u32(const void* p) {
    return (uint32_t)__cvta_generic_to_shared(p);
}
__device__ __forceinline__ void cp16(uint32_t s, const void* g) {
    asm volatile("cp.async.cg.shared.global [%0], [%1], 16;\n" :: "r"(s), "l"(g));
}
__device__ __forceinline__ void cp_commit() { asm volatile("cp.async.commit_group;\n"); }
template<int N> __device__ __forceinline__ void cp_wait() {
    asm volatile("cp.async.wait_group %0;\n" :: "n"(N));
}
__device__ __forceinline__ void mma_tf32(float c[4],
    uint32_t a0, uint32_t a1, uint32_t a2, uint32_t a3, uint32_t b0, uint32_t b1)
{
    asm volatile(
        "mma.sync.aligned.m16n8k8.row.col.f32.tf32.tf32.f32 "
        "{%0,%1,%2,%3},{%4,%5,%6,%7},{%8,%9},{%0,%1,%2,%3};\n"
        : "+f"(c[0]), "+f"(c[1]), "+f"(c[2]), "+f"(c[3])
        : "r"(a0), "r"(a1), "r"(a2), "r"(a3), "r"(b0), "r"(b1));
}
__device__ __forceinline__ void mma_bf16(float c[4],
    uint32_t a0, uint32_t a1, uint32_t a2, uint32_t a3, uint32_t b0, uint32_t b1)
{
    asm volatile(
        "mma.sync.aligned.m16n8k16.row.col.f32.bf16.bf16.f32 "
        "{%0,%1,%2,%3},{%4,%5,%6,%7},{%8,%9},{%0,%1,%2,%3};\n"
        : "+f"(c[0]), "+f"(c[1]), "+f"(c[2]), "+f"(c[3])
        : "r"(a0), "r"(a1), "r"(a2), "r"(a3), "r"(b0), "r"(b1));
}
__device__ __forceinline__ void ldsm_x4(uint32_t& r0, uint32_t& r1,
                                        uint32_t& r2, uint32_t& r3, uint32_t a)
{
    asm volatile("ldmatrix.sync.aligned.m8n8.x4.shared.b16 {%0,%1,%2,%3}, [%4];\n"
                 : "=r"(r0), "=r"(r1), "=r"(r2), "=r"(r3) : "r"(a));
}
__device__ __forceinline__ void ldsm_x4_t(uint32_t& r0, uint32_t& r1,
                                          uint32_t& r2, uint32_t& r3, uint32_t a)
{
    asm volatile("ldmatrix.sync.aligned.m8n8.x4.trans.shared.b16 {%0,%1,%2,%3}, [%4];\n"
                 : "=r"(r0), "=r"(r1), "=r"(r2), "=r"(r3) : "r"(a));
}
__device__ __forceinline__ uint32_t packbf(float x, float y) {
    __nv_bfloat162 t = __floats2bfloat162_rn(x, y);
    return *(uint32_t*)&t;
}

// load 128 rows x 16 floats tile into smem [row*20 + col] via cp.async
__device__ __forceinline__ void cpa_tile128x16(float* dst, const float* src, int ld) {
    const int tid = threadIdx.x;
    const int row = tid >> 2;
    const int c4  = (tid & 3) * 4;
    cp16(smem_u32(dst + row * 20 + c4),        src + (size_t)row * ld + c4);
    cp16(smem_u32(dst + (row + 64) * 20 + c4), src + (size_t)(row + 64) * ld + c4);
}

// load 128 rows x 64 bf16 into smem [row*72 + col] via cp.async (4 cp16/thread)
__device__ __forceinline__ void cpa_bf128x64(__nv_bfloat16* dst, const __nv_bfloat16* src) {
    const int tid = threadIdx.x;
#pragma unroll
    for (int i = 0; i < 4; i++) {
        int c = tid + i * 256;
        int r = c >> 3, col = (c & 7) * 8;
        cp16(smem_u32(dst + r * 72 + col), src + (size_t)r * HD_ + col);
    }
}

// 128x128 block-tile compute on one BK=16 chunk (8 warps: 2m x 4n, warp tile 64x32)
__device__ __forceinline__ void mma_block_128x128(
    const float* As, const float* Bs,
    int warp_m, int warp_n, int gid, int tig, float acc[4][4][4])
{
#pragma unroll
    for (int ks = 0; ks < 16; ks += 8) {
        uint32_t a[4][4], b[4][2];
#pragma unroll
        for (int i = 0; i < 4; i++) {
            int r = warp_m * 64 + i * 16 + gid;
            a[i][0] = __float_as_uint(As[r * 20 + ks + tig]);
            a[i][1] = __float_as_uint(As[(r + 8) * 20 + ks + tig]);
            a[i][2] = __float_as_uint(As[r * 20 + ks + tig + 4]);
            a[i][3] = __float_as_uint(As[(r + 8) * 20 + ks + tig + 4]);
        }
#pragma unroll
        for (int j = 0; j < 4; j++) {
            int n = warp_n * 32 + j * 8 + gid;
            b[j][0] = __float_as_uint(Bs[n * 20 + ks + tig]);
            b[j][1] = __float_as_uint(Bs[n * 20 + ks + tig + 4]);
        }
#pragma unroll
        for (int i = 0; i < 4; i++)
#pragma unroll
            for (int j = 0; j < 4; j++)
                mma_tf32(acc[i][j], a[i][0], a[i][1], a[i][2], a[i][3], b[j][0], b[j][1]);
    }
}

// =================================================================
// K0: relsum = rel_pos + rel_2d   (16M floats)
// =================================================================
__global__ void __launch_bounds__(256) relsum_kernel(
    const float4* __restrict__ a, const float4* __restrict__ b)
{
    size_t i = (size_t)blockIdx.x * 256 + threadIdx.x;
    float4 x = a[i], y = b[i];
    x.x += y.x; x.y += y.y; x.z += y.z; x.w += y.w;
    ((float4*)g_bias)[i] = x;
}

// =================================================================
// K1: QKV projection (tf32). Outputs bf16 head-layout q/k/v.
// =================================================================
__device__ __forceinline__ void qkv_store(int bb, int ss, int n, float2 v,
                                          const float* qb, const float* vb)
{
    if (n < HID_) {
        int h = n >> 6, d = n & 63;
        *(__nv_bfloat162*)&g_q[(((size_t)(bb * NH_ + h)) * S_ + ss) * HD_ + d] =
            __floats2bfloat162_rn((v.x + qb[n]) * 0.125f, (v.y + qb[n + 1]) * 0.125f);
    } else if (n < 2 * HID_) {
        int nn = n - HID_;
        int h = nn >> 6, d = nn & 63;
        *(__nv_bfloat162*)&g_k[(((size_t)(bb * NH_ + h)) * S_ + ss) * HD_ + d] =
            __floats2bfloat162_rn(v.x, v.y);
    } else {
        int nn = n - 2 * HID_;
        int h = nn >> 6, d = nn & 63;
        *(__nv_bfloat162*)&g_v[(((size_t)(bb * NH_ + h)) * S_ + ss) * HD_ + d] =
            __floats2bfloat162_rn(v.x + vb[nn], v.y + vb[nn + 1]);
    }
}

__global__ void __launch_bounds__(256) qkv_gemm_kernel(
    const float* __restrict__ X, const float* __restrict__ W,
    const float* __restrict__ qb, const float* __restrict__ vb)
{
    __shared__ float As[2][128 * 20];
    __shared__ float Bs[2][128 * 20];
    const int bm = blockIdx.y * 128, bn = blockIdx.x * 128;
    const int tid = threadIdx.x, wid = tid >> 5, lane = tid & 31;
    const int gid = lane >> 2, tig = lane & 3;
    const int warp_m = wid >> 2, warp_n = wid & 3;

    float acc[4][4][4];
#pragma unroll
    for (int i = 0; i < 4; i++)
#pragma unroll
        for (int j = 0; j < 4; j++)
#pragma unroll
            for (int k = 0; k < 4; k++) acc[i][j][k] = 0.f;

    const float* Abase = X + (size_t)bm * HID_;
    const float* Bbase = W + (size_t)bn * HID_;

    cpa_tile128x16(As[0], Abase, HID_);
    cpa_tile128x16(Bs[0], Bbase, HID_);
    cp_commit();

    const int NC = HID_ / 16;
    for (int c = 0; c < NC; c++) {
        int cur = c & 1;
        if (c + 1 < NC) {
            cpa_tile128x16(As[cur ^ 1], Abase + (c + 1) * 16, HID_);
            cpa_tile128x16(Bs[cur ^ 1], Bbase + (c + 1) * 16, HID_);
            cp_commit();
            cp_wait<1>();
        } else {
            cp_wait<0>();
        }
        __syncthreads();
        mma_block_128x128(As[cur], Bs[cur], warp_m, warp_n, gid, tig, acc);
        __syncthreads();
    }

    const int bb = bm >> 10, ss0 = bm & 1023;
#pragma unroll
    for (int i = 0; i < 4; i++) {
        int r = warp_m * 64 + i * 16 + gid;
#pragma unroll
        for (int j = 0; j < 4; j++) {
            int n = bn + warp_n * 32 + j * 8 + tig * 2;
            qkv_store(bb, ss0 + r,     n, make_float2(acc[i][j][0], acc[i][j][1]), qb, vb);
            qkv_store(bb, ss0 + r + 8, n, make_float2(acc[i][j][2], acc[i][j][3]), qb, vb);
        }
    }
}

// =================================================================
// K2 (FUSED, bf16): flash attention with precomputed bias.
// CTA = (b, qt, h), 128 q-rows; 8 K/V tiles of 128; online softmax.
// smem: Qs[128][72] Ks[2][128][72] Vs[2][128][72] bf16 + maskf[1024]
// =================================================================
#define PITCH 72
#define TILE_E (128 * PITCH)
#define FUSED_SMEM (5 * TILE_E * 2 + 1024 * 4)

extern __shared__ char dynsmem[];

__global__ void __launch_bounds__(256, 1) fused_attn_kernel(
    const unsigned char* __restrict__ mask)
{
    const int b  = blockIdx.x;
    const int qt = blockIdx.y;
    const int h  = blockIdx.z;
    const int bh = b * NH_ + h;

    __nv_bfloat16* Qs = (__nv_bfloat16*)dynsmem;          // [128][72]
    __nv_bfloat16* Ks = Qs + TILE_E;                      // 2 x [128][72]
    __nv_bfloat16* Vs = Ks + 2 * TILE_E;                  // 2 x [128][72]
    float* smaskf = (float*)(Vs + 2 * TILE_E);            // [1024]

    const int tid = threadIdx.x, wid = tid >> 5, lane = tid & 31;
    const int gid = lane >> 2, tig = lane & 3;

    const __nv_bfloat16* Qg = g_q + (size_t)bh * S_ * HD_ + (size_t)(qt * 128) * HD_;
    const __nv_bfloat16* Kg = g_k + (size_t)bh * S_ * HD_;
    const __nv_bfloat16* Vg = g_v + (size_t)bh * S_ * HD_;

    // prologue
    cpa_bf128x64(Qs, Qg);
    cp_commit();
    cpa_bf128x64(Ks, Kg);
    cpa_bf128x64(Vs, Vg);
    cp_commit();

    // mask -> smem floats (full 1024 row, once)
    const unsigned char* mrow = mask + b * S_;
#pragma unroll
    for (int i = 0; i < 4; i++)
        smaskf[tid * 4 + i] = mrow[tid * 4 + i] ? -1e30f : 0.f;

    cp_wait<1>();        // Qs ready
    __syncthreads();

    // ldmatrix lane addressing: row = base + (lane&15), col = +8*(lane>>4)
    const int lrow = lane & 15;
    const int lcol = (lane >> 4) << 3;

    // Q fragments: warp owns rows wid*16..+15
    uint32_t qA[4][4];
#pragma unroll
    for (int kk = 0; kk < 4; kk++)
        ldsm_x4(qA[kk][0], qA[kk][1], qA[kk][2], qA[kk][3],
                smem_u32(Qs + (wid * 16 + lrow) * PITCH + kk * 16 + lcol));

    // online softmax state: rows ra = qt*128 + wid*16 + gid, rb = ra+8
    float m_a = -1e30f, m_b = -1e30f;
    float l_a = 0.f,    l_b = 0.f;
    float cacc[8][4];
#pragma unroll
    for (int jj = 0; jj < 8; jj++)
#pragma unroll
        for (int k = 0; k < 4; k++) cacc[jj][k] = 0.f;

    const int r0 = wid * 16 + gid;
    const int ra = qt * 128 + r0;
    const float* biasA = g_bias + ((size_t)h * S_ + ra) * S_;
    const float* biasB = biasA + 8 * S_;

    for (int kt = 0; kt < 8; kt++) {
        const int cur = kt & 1;
        cp_wait<0>();
        __syncthreads();   // tile kt resident; all warps done with kt-1 buffers

        if (kt + 1 < 8) {
            cpa_bf128x64(Ks + (cur ^ 1) * TILE_E, Kg + (size_t)(kt + 1) * 128 * HD_);
            cpa_bf128x64(Vs + (cur ^ 1) * TILE_E, Vg + (size_t)(kt + 1) * 128 * HD_);
            cp_commit();
        }

        // ---- S = Q . K^T  (warp: 16 x 128) ----
        const __nv_bfloat16* Kp = Ks + cur * TILE_E;
        float s[16][4];
#pragma unroll
        for (int j = 0; j < 16; j++)
#pragma unroll
            for (int k = 0; k < 4; k++) s[j][k] = 0.f;
#pragma unroll
        for (int kk = 0; kk < 4; kk++) {
#pragma unroll
            for (int jp = 0; jp < 8; jp++) {
                uint32_t b0, b1, b2, b3;
                ldsm_x4(b0, b1, b2, b3,
                        smem_u32(Kp + (jp * 16 + lrow) * PITCH + kk * 16 + lcol));
                mma_bf16(s[2 * jp],     qA[kk][0], qA[kk][1], qA[kk][2], qA[kk][3], b0, b2);
                mma_bf16(s[2 * jp + 1], qA[kk][0], qA[kk][1], qA[kk][2], qA[kk][3], b1, b3);
            }
        }

        // ---- bias + mask; tile row max ----
        float mxa = -1e30f, mxb = -1e30f;
        const size_t coff = (size_t)kt * 128;
#pragma unroll
        for (int j = 0; j < 16; j++) {
            int n = j * 8 + tig * 2;
            float2 bA = *(const float2*)&biasA[coff + n];
            float2 bB = *(const float2*)&biasB[coff + n];
            float m0 = smaskf[coff + n], m1 = smaskf[coff + n + 1];
            s[j][0] += bA.x + m0;
            s[j][1] += bA.y + m1;
            s[j][2] += bB.x + m0;
            s[j][3] += bB.y + m1;
            mxa = fmaxf(mxa, fmaxf(s[j][0], s[j][1]));
            mxb = fmaxf(mxb, fmaxf(s[j][2], s[j][3]));
        }
        mxa = fmaxf(mxa, __shfl_xor_sync(0xffffffffu, mxa, 1));
        mxa = fmaxf(mxa, __shfl_xor_sync(0xffffffffu, mxa, 2));
        mxb = fmaxf(mxb, __shfl_xor_sync(0xffffffffu, mxb, 1));
        mxb = fmaxf(mxb, __shfl_xor_sync(0xffffffffu, mxb, 2));

        float mna = fmaxf(m_a, mxa), mnb = fmaxf(m_b, mxb);
        float sca = __expf(m_a - mna), scb = __expf(m_b - mnb);
        m_a = mna; m_b = mnb;

        float suma = 0.f, sumb = 0.f;
#pragma unroll
        for (int j = 0; j < 16; j++) {
            s[j][0] = __expf(s[j][0] - m_a);
            s[j][1] = __expf(s[j][1] - m_a);
            s[j][2] = __expf(s[j][2] - m_b);
            s[j][3] = __expf(s[j][3] - m_b);
            suma += s[j][0] + s[j][1];
            sumb += s[j][2] + s[j][3];
        }
        l_a = l_a * sca + suma;
        l_b = l_b * scb + sumb;
#pragma unroll
        for (int jj = 0; jj < 8; jj++) {
            cacc[jj][0] *= sca; cacc[jj][1] *= sca;
            cacc[jj][2] *= scb; cacc[jj][3] *= scb;
        }

        // ---- ctx += P . V  (P from s[] via direct bf16 pack; V^T via ldmatrix.trans) ----
        const __nv_bfloat16* Vp = Vs + cur * TILE_E;
#pragma unroll
        for (int jc = 0; jc < 8; jc++) {
            uint32_t a0 = packbf(s[2 * jc][0],     s[2 * jc][1]);
            uint32_t a1 = packbf(s[2 * jc][2],     s[2 * jc][3]);
            uint32_t a2 = packbf(s[2 * jc + 1][0], s[2 * jc + 1][1]);
            uint32_t a3 = packbf(s[2 * jc + 1][2], s[2 * jc + 1][3]);
#pragma unroll
            for (int dp = 0; dp < 4; dp++) {
                uint32_t v0, v1, v2, v3;
                ldsm_x4_t(v0, v1, v2, v3,
                          smem_u32(Vp + (jc * 16 + lrow) * PITCH + dp * 16 + lcol));
                mma_bf16(cacc[2 * dp],     a0, a1, a2, a3, v0, v1);
                mma_bf16(cacc[2 * dp + 1], a0, a1, a2, a3, v2, v3);
            }
        }
    }

    // final: reduce l across 4 lanes, normalize, write ctx [b,s,h,d] (fp32)
    l_a += __shfl_xor_sync(0xffffffffu, l_a, 1);
    l_a += __shfl_xor_sync(0xffffffffu, l_a, 2);
    l_b += __shfl_xor_sync(0xffffffffu, l_b, 1);
    l_b += __shfl_xor_sync(0xffffffffu, l_b, 2);
    float inva = 1.0f / l_a, invb = 1.0f / l_b;

    const size_t obase_a = (((size_t)b * S_ + ra) * NH_ + h) * HD_;
    const size_t obase_b = (((size_t)b * S_ + ra + 8) * NH_ + h) * HD_;
#pragma unroll
    for (int jj = 0; jj < 8; jj++) {
        int d = jj * 8 + tig * 2;
        *(float2*)&g_ctx[obase_a + d] =
            make_float2(cacc[jj][0] * inva, cacc[jj][1] * inva);
        *(float2*)&g_ctx[obase_b + d] =
            make_float2(cacc[jj][2] * invb, cacc[jj][3] * invb);
    }
}

// =================================================================
// K3: out projection + bias + residual (tf32). M=8192, N=1024, K=1024
// =================================================================
__global__ void __launch_bounds__(256) outproj_kernel(
    const float* __restrict__ Wout, const float* __restrict__ b_out,
    const float* __restrict__ X)
{
    __shared__ float As[2][128 * 20];
    __shared__ float Bs[2][128 * 20];
    const int bm = blockIdx.y * 128, bn = blockIdx.x * 128;
    const int tid = threadIdx.x, wid = tid >> 5, lane = tid & 31;
    const int gid = lane >> 2, tig = lane & 3;
    const int warp_m = wid >> 2, warp_n = wid & 3;

    float acc[4][4][4];
#pragma unroll
    for (int i = 0; i < 4; i++)
#pragma unroll
        for (int j = 0; j < 4; j++)
#pragma unroll
            for (int k = 0; k < 4; k++) acc[i][j][k] = 0.f;

    const float* Abase = g_ctx + (size_t)bm * HID_;
    const float* Bbase = Wout + (size_t)bn * HID_;

    cpa_tile128x16(As[0], Abase, HID_);
    cpa_tile128x16(Bs[0], Bbase, HID_);
    cp_commit();

    const int NC = HID_ / 16;
    for (int c = 0; c < NC; c++) {
        int cur = c & 1;
        if (c + 1 < NC) {
            cpa_tile128x16(As[cur ^ 1], Abase + (c + 1) * 16, HID_);
            cpa_tile128x16(Bs[cur ^ 1], Bbase + (c + 1) * 16, HID_);
            cp_commit();
            cp_wait<1>();
        } else {
            cp_wait<0>();
        }
        __syncthreads();
        mma_block_128x128(As[cur], Bs[cur], warp_m, warp_n, gid, tig, acc);
        __syncthreads();
    }

#pragma unroll
    for (int i = 0; i < 4; i++) {
        int r0 = bm + warp_m * 64 + i * 16 + gid;
#pragma unroll
        for (int j = 0; j < 4; j++) {
            int n = bn + warp_n * 32 + j * 8 + tig * 2;
            float2 x0 = *(const float2*)&X[(size_t)r0 * HID_ + n];
            float2 x1 = *(const float2*)&X[(size_t)(r0 + 8) * HID_ + n];
            float b0 = b_out[n], b1 = b_out[n + 1];
            *(float2*)&g_h[(size_t)r0 * HID_ + n] =
                make_float2(acc[i][j][0] + b0 + x0.x, acc[i][j][1] + b1 + x0.y);
            *(float2*)&g_h[(size_t)(r0 + 8) * HID_ + n] =
                make_float2(acc[i][j][2] + b0 + x1.x, acc[i][j][3] + b1 + x1.y);
        }
    }
}

// =================================================================
// K4: LayerNorm per row of g_h -> d_out
// =================================================================
__global__ void __launch_bounds__(256) layernorm_kernel(
    const float* __restrict__ gamma, const float* __restrict__ beta,
    float* __restrict__ out)
{
    const size_t row = blockIdx.x;
    const float* hp = g_h + row * HID_;
    const int tid = threadIdx.x;
    const int n = tid * 4;

    float4 v = *(const float4*)(hp + n);
    __shared__ float red[256];

    red[tid] = v.x + v.y + v.z + v.w;
    __syncthreads();
    for (int s = 128; s > 0; s >>= 1) {
        if (tid < s) red[tid] += red[tid + s];
        __syncthreads();
    }
    float mean = red[0] * (1.0f / HID_);
    __syncthreads();

    float dx = v.x - mean, dy = v.y - mean, dz = v.z - mean, dw = v.w - mean;
    red[tid] = dx * dx + dy * dy + dz * dz + dw * dw;
    __syncthreads();
    for (int s = 128; s > 0; s >>= 1) {
        if (tid < s) red[tid] += red[tid + s];
        __syncthreads();
    }
    float inv = rsqrtf(red[0] * (1.0f / HID_) + 1e-12f);

    float4 o;
    o.x = dx * inv * gamma[n + 0] + beta[n + 0];
    o.y = dy * inv * gamma[n + 1] + beta[n + 1];
    o.z = dz * inv * gamma[n + 2] + beta[n + 2];
    o.w = dw * inv * gamma[n + 3] + beta[n + 3];
    *(float4*)(out + row * HID_ + n) = o;
}

// =================================================================
extern "C" void kernel_launch(void* const* d_in, const int* in_sizes, int n_in,
                              void* d_out, int out_size)
{
    const float*         x       = (const float*)d_in[0];
    const unsigned char* mask    = (const unsigned char*)d_in[1];
    const float*         rel_pos = (const float*)d_in[2];
    const float*         rel2d   = (const float*)d_in[3];
    const float*         w_qkv   = (const float*)d_in[4];
    const float*         q_bias  = (const float*)d_in[5];
    const float*         v_bias  = (const float*)d_in[6];
    const float*         w_out   = (const float*)d_in[7];
    const float*         b_out   = (const float*)d_in[8];
    const float*         gamma   = (const float*)d_in[9];
    const float*         beta    = (const float*)d_in[10];
    float*               out     = (float*)d_out;

    cudaFuncSetAttribute(fused_attn_kernel,
                         cudaFuncAttributeMaxDynamicSharedMemorySize, FUSED_SMEM);

    relsum_kernel<<<(NH_ * S_ * S_ / 4) / 256, 256>>>(
        (const float4*)rel_pos, (const float4*)rel2d);
    qkv_gemm_kernel<<<dim3(24, 64), 256>>>(x, w_qkv, q_bias, v_bias);
    fused_attn_kernel<<<dim3(B_, 8, NH_), 256, FUSED_SMEM>>>(mask);
    outproj_kernel<<<dim3(8, 64), 256>>>(w_out, b_out, x);
    layernorm_kernel<<<dim3(B_ * S_), 256>>>(gamma, beta, out);
}

// round 11
// speedup vs baseline: 1.7226x; 1.3912x over previous
#include <cuda_runtime.h>
#include <cuda_bf16.h>
#include <cstdint>

#define B_   8
#define S_   1024
#define HID_ 1024
#define NH_  16
#define HD_  64

// ---------------- scratch (no allocations allowed) ----------------
__device__ __align__(16) __nv_bfloat16 g_q[B_ * NH_ * S_ * HD_];   // pre-scaled 1/8, +q_bias
__device__ __align__(16) __nv_bfloat16 g_k[B_ * NH_ * S_ * HD_];
__device__ __align__(16) __nv_bfloat16 g_v[B_ * NH_ * S_ * HD_];
__device__ __align__(16) float g_bias[(size_t)NH_ * S_ * S_];      // rel_pos + rel_2d
__device__ __align__(16) __nv_bfloat16 g_ctx[B_ * S_ * HID_];      // [b,s,h,d] bf16
__device__ __align__(16) float g_h[B_ * S_ * HID_];
__device__ __align__(16) __nv_bfloat16 g_xb[B_ * S_ * HID_];       // x in bf16
__device__ __align__(16) __nv_bfloat16 g_wqkvb[3 * HID_ * HID_];   // w_qkv bf16
__device__ __align__(16) __nv_bfloat16 g_woutb[HID_ * HID_];       // w_out bf16

// ---------------- helpers ----------------
__device__ __forceinline__ uint32_t smem_u32(const void* p) {
    return (uint32_t)__cvta_generic_to_shared(p);
}
__device__ __forceinline__ void cp16(uint32_t s, const void* g) {
    asm volatile("cp.async.cg.shared.global [%0], [%1], 16;\n" :: "r"(s), "l"(g));
}
__device__ __forceinline__ void cp_commit() { asm volatile("cp.async.commit_group;\n"); }
template<int N> __device__ __forceinline__ void cp_wait() {
    asm volatile("cp.async.wait_group %0;\n" :: "n"(N));
}
__device__ __forceinline__ void mma_bf16(float c[4],
    uint32_t a0, uint32_t a1, uint32_t a2, uint32_t a3, uint32_t b0, uint32_t b1)
{
    asm volatile(
        "mma.sync.aligned.m16n8k16.row.col.f32.bf16.bf16.f32 "
        "{%0,%1,%2,%3},{%4,%5,%6,%7},{%8,%9},{%0,%1,%2,%3};\n"
        : "+f"(c[0]), "+f"(c[1]), "+f"(c[2]), "+f"(c[3])
        : "r"(a0), "r"(a1), "r"(a2), "r"(a3), "r"(b0), "r"(b1));
}
__device__ __forceinline__ void ldsm_x4(uint32_t& r0, uint32_t& r1,
                                        uint32_t& r2, uint32_t& r3, uint32_t a)
{
    asm volatile("ldmatrix.sync.aligned.m8n8.x4.shared.b16 {%0,%1,%2,%3}, [%4];\n"
                 : "=r"(r0), "=r"(r1), "=r"(r2), "=r"(r3) : "r"(a));
}
__device__ __forceinline__ void ldsm_x4_t(uint32_t& r0, uint32_t& r1,
                                          uint32_t& r2, uint32_t& r3, uint32_t a)
{
    asm volatile("ldmatrix.sync.aligned.m8n8.x4.trans.shared.b16 {%0,%1,%2,%3}, [%4];\n"
                 : "=r"(r0), "=r"(r1), "=r"(r2), "=r"(r3) : "r"(a));
}
__device__ __forceinline__ uint32_t packbf(float x, float y) {
    __nv_bfloat162 t = __floats2bfloat162_rn(x, y);
    return *(uint32_t*)&t;
}

// =================================================================
// converts: fp32 -> bf16 into device globals (referenced from DEVICE code)
// =================================================================
__global__ void __launch_bounds__(256) f2bf_x_kernel(const float4* __restrict__ src) {
    size_t i = (size_t)blockIdx.x * 256 + threadIdx.x;
    float4 v = src[i];
    __nv_bfloat162* dst = (__nv_bfloat162*)g_xb;
    dst[2 * i]     = __floats2bfloat162_rn(v.x, v.y);
    dst[2 * i + 1] = __floats2bfloat162_rn(v.z, v.w);
}
__global__ void __launch_bounds__(256) f2bf_wqkv_kernel(const float4* __restrict__ src) {
    size_t i = (size_t)blockIdx.x * 256 + threadIdx.x;
    float4 v = src[i];
    __nv_bfloat162* dst = (__nv_bfloat162*)g_wqkvb;
    dst[2 * i]     = __floats2bfloat162_rn(v.x, v.y);
    dst[2 * i + 1] = __floats2bfloat162_rn(v.z, v.w);
}
__global__ void __launch_bounds__(256) f2bf_wout_kernel(const float4* __restrict__ src) {
    size_t i = (size_t)blockIdx.x * 256 + threadIdx.x;
    float4 v = src[i];
    __nv_bfloat162* dst = (__nv_bfloat162*)g_woutb;
    dst[2 * i]     = __floats2bfloat162_rn(v.x, v.y);
    dst[2 * i + 1] = __floats2bfloat162_rn(v.z, v.w);
}

// =================================================================
// K0: relsum = rel_pos + rel_2d
// =================================================================
__global__ void __launch_bounds__(256) relsum_kernel(
    const float4* __restrict__ a, const float4* __restrict__ b)
{
    size_t i = (size_t)blockIdx.x * 256 + threadIdx.x;
    float4 x = a[i], y = b[i];
    x.x += y.x; x.y += y.y; x.z += y.z; x.w += y.w;
    ((float4*)g_bias)[i] = x;
}

// ---------------- bf16 GEMM building blocks (BK=32, pitch 40) ----------------
#define GP 40
__device__ __forceinline__ void cpa_bf128x32(__nv_bfloat16* dst,
                                             const __nv_bfloat16* src, int ld)
{
    const int tid = threadIdx.x;
#pragma unroll
    for (int i = 0; i < 2; i++) {
        int idx = tid + i * 256;
        int r = idx >> 2, c = (idx & 3) * 8;
        cp16(smem_u32(dst + r * GP + c), src + (size_t)r * ld + c);
    }
}

__device__ __forceinline__ void mma_block_bf16(
    const __nv_bfloat16* As, const __nv_bfloat16* Bs,
    int warp_m, int warp_n, int lrow, int lcol, float acc[4][4][4])
{
#pragma unroll
    for (int ks = 0; ks < 2; ks++) {
        uint32_t a[4][4], bfr[2][4];
#pragma unroll
        for (int i = 0; i < 4; i++)
            ldsm_x4(a[i][0], a[i][1], a[i][2], a[i][3],
                    smem_u32(As + (warp_m * 64 + i * 16 + lrow) * GP + ks * 16 + lcol));
#pragma unroll
        for (int g = 0; g < 2; g++)
            ldsm_x4(bfr[g][0], bfr[g][1], bfr[g][2], bfr[g][3],
                    smem_u32(Bs + (warp_n * 32 + g * 16 + lrow) * GP + ks * 16 + lcol));
#pragma unroll
        for (int i = 0; i < 4; i++)
#pragma unroll
            for (int g = 0; g < 2; g++) {
                mma_bf16(acc[i][2 * g],     a[i][0], a[i][1], a[i][2], a[i][3],
                         bfr[g][0], bfr[g][2]);
                mma_bf16(acc[i][2 * g + 1], a[i][0], a[i][1], a[i][2], a[i][3],
                         bfr[g][1], bfr[g][3]);
            }
    }
}

// =================================================================
// K1: QKV projection (bf16). M=8192, N=3072, K=1024
// =================================================================
__device__ __forceinline__ void qkv_store(int bb, int ss, int n, float2 v,
                                          const float* qb, const float* vb)
{
    if (n < HID_) {
        int h = n >> 6, d = n & 63;
        *(__nv_bfloat162*)&g_q[(((size_t)(bb * NH_ + h)) * S_ + ss) * HD_ + d] =
            __floats2bfloat162_rn((v.x + qb[n]) * 0.125f, (v.y + qb[n + 1]) * 0.125f);
    } else if (n < 2 * HID_) {
        int nn = n - HID_;
        int h = nn >> 6, d = nn & 63;
        *(__nv_bfloat162*)&g_k[(((size_t)(bb * NH_ + h)) * S_ + ss) * HD_ + d] =
            __floats2bfloat162_rn(v.x, v.y);
    } else {
        int nn = n - 2 * HID_;
        int h = nn >> 6, d = nn & 63;
        *(__nv_bfloat162*)&g_v[(((size_t)(bb * NH_ + h)) * S_ + ss) * HD_ + d] =
            __floats2bfloat162_rn(v.x + vb[nn], v.y + vb[nn + 1]);
    }
}

__global__ void __launch_bounds__(256) qkv_gemm_kernel(
    const float* __restrict__ qb, const float* __restrict__ vb)
{
    __shared__ __align__(16) __nv_bfloat16 As[2][128 * GP];
    __shared__ __align__(16) __nv_bfloat16 Bs[2][128 * GP];
    const int bm = blockIdx.y * 128, bn = blockIdx.x * 128;
    const int tid = threadIdx.x, wid = tid >> 5, lane = tid & 31;
    const int gid = lane >> 2, tig = lane & 3;
    const int lrow = lane & 15, lcol = (lane >> 4) << 3;
    const int warp_m = wid >> 2, warp_n = wid & 3;

    float acc[4][4][4];
#pragma unroll
    for (int i = 0; i < 4; i++)
#pragma unroll
        for (int j = 0; j < 4; j++)
#pragma unroll
            for (int k = 0; k < 4; k++) acc[i][j][k] = 0.f;

    const __nv_bfloat16* Abase = g_xb + (size_t)bm * HID_;
    const __nv_bfloat16* Bbase = g_wqkvb + (size_t)bn * HID_;

    cpa_bf128x32(As[0], Abase, HID_);
    cpa_bf128x32(Bs[0], Bbase, HID_);
    cp_commit();

    const int NC = HID_ / 32;
    for (int c = 0; c < NC; c++) {
        int cur = c & 1;
        if (c + 1 < NC) {
            cpa_bf128x32(As[cur ^ 1], Abase + (c + 1) * 32, HID_);
            cpa_bf128x32(Bs[cur ^ 1], Bbase + (c + 1) * 32, HID_);
            cp_commit();
            cp_wait<1>();
        } else {
            cp_wait<0>();
        }
        __syncthreads();
        mma_block_bf16(As[cur], Bs[cur], warp_m, warp_n, lrow, lcol, acc);
        __syncthreads();
    }

    const int bb = bm >> 10, ss0 = bm & 1023;
#pragma unroll
    for (int i = 0; i < 4; i++) {
        int r = warp_m * 64 + i * 16 + gid;
#pragma unroll
        for (int j = 0; j < 4; j++) {
            int n = bn + warp_n * 32 + j * 8 + tig * 2;
            qkv_store(bb, ss0 + r,     n, make_float2(acc[i][j][0], acc[i][j][1]), qb, vb);
            qkv_store(bb, ss0 + r + 8, n, make_float2(acc[i][j][2], acc[i][j][3]), qb, vb);
        }
    }
}

// =================================================================
// K2 (FUSED, bf16): flash attention with precomputed bias.
// =================================================================
#define PITCH 72
#define TILE_E (128 * PITCH)
#define FUSED_SMEM (5 * TILE_E * 2 + 1024 * 4)

extern __shared__ char dynsmem[];

__global__ void __launch_bounds__(256, 1) fused_attn_kernel(
    const unsigned char* __restrict__ mask)
{
    const int b  = blockIdx.x;
    const int qt = blockIdx.y;
    const int h  = blockIdx.z;
    const int bh = b * NH_ + h;

    __nv_bfloat16* Qs = (__nv_bfloat16*)dynsmem;          // [128][72]
    __nv_bfloat16* Ks = Qs + TILE_E;                      // 2 x [128][72]
    __nv_bfloat16* Vs = Ks + 2 * TILE_E;                  // 2 x [128][72]
    float* smaskf = (float*)(Vs + 2 * TILE_E);            // [1024]

    const int tid = threadIdx.x, wid = tid >> 5, lane = tid & 31;
    const int gid = lane >> 2, tig = lane & 3;

    const __nv_bfloat16* Qg = g_q + (size_t)bh * S_ * HD_ + (size_t)(qt * 128) * HD_;
    const __nv_bfloat16* Kg = g_k + (size_t)bh * S_ * HD_;
    const __nv_bfloat16* Vg = g_v + (size_t)bh * S_ * HD_;

    // prologue (128x64 bf16 tiles, 4 cp16/thread)
    {
#pragma unroll
        for (int i = 0; i < 4; i++) {
            int c = tid + i * 256;
            int r = c >> 3, col = (c & 7) * 8;
            cp16(smem_u32(Qs + r * PITCH + col), Qg + (size_t)r * HD_ + col);
        }
        cp_commit();
#pragma unroll
        for (int i = 0; i < 4; i++) {
            int c = tid + i * 256;
            int r = c >> 3, col = (c & 7) * 8;
            cp16(smem_u32(Ks + r * PITCH + col), Kg + (size_t)r * HD_ + col);
        }
#pragma unroll
        for (int i = 0; i < 4; i++) {
            int c = tid + i * 256;
            int r = c >> 3, col = (c & 7) * 8;
            cp16(smem_u32(Vs + r * PITCH + col), Vg + (size_t)r * HD_ + col);
        }
        cp_commit();
    }

    const unsigned char* mrow = mask + b * S_;
#pragma unroll
    for (int i = 0; i < 4; i++)
        smaskf[tid * 4 + i] = mrow[tid * 4 + i] ? -1e30f : 0.f;

    cp_wait<1>();        // Qs ready
    __syncthreads();

    const int lrow = lane & 15;
    const int lcol = (lane >> 4) << 3;

    uint32_t qA[4][4];
#pragma unroll
    for (int kk = 0; kk < 4; kk++)
        ldsm_x4(qA[kk][0], qA[kk][1], qA[kk][2], qA[kk][3],
                smem_u32(Qs + (wid * 16 + lrow) * PITCH + kk * 16 + lcol));

    float m_a = -1e30f, m_b = -1e30f;
    float l_a = 0.f,    l_b = 0.f;
    float cacc[8][4];
#pragma unroll
    for (int jj = 0; jj < 8; jj++)
#pragma unroll
        for (int k = 0; k < 4; k++) cacc[jj][k] = 0.f;

    const int r0 = wid * 16 + gid;
    const int ra = qt * 128 + r0;
    const float* biasA = g_bias + ((size_t)h * S_ + ra) * S_;
    const float* biasB = biasA + 8 * S_;

    for (int kt = 0; kt < 8; kt++) {
        const int cur = kt & 1;
        cp_wait<0>();
        __syncthreads();

        if (kt + 1 < 8) {
            const __nv_bfloat16* Kn = Kg + (size_t)(kt + 1) * 128 * HD_;
            const __nv_bfloat16* Vn = Vg + (size_t)(kt + 1) * 128 * HD_;
            __nv_bfloat16* Kd = Ks + (cur ^ 1) * TILE_E;
            __nv_bfloat16* Vd = Vs + (cur ^ 1) * TILE_E;
#pragma unroll
            for (int i = 0; i < 4; i++) {
                int c = tid + i * 256;
                int r = c >> 3, col = (c & 7) * 8;
                cp16(smem_u32(Kd + r * PITCH + col), Kn + (size_t)r * HD_ + col);
            }
#pragma unroll
            for (int i = 0; i < 4; i++) {
                int c = tid + i * 256;
                int r = c >> 3, col = (c & 7) * 8;
                cp16(smem_u32(Vd + r * PITCH + col), Vn + (size_t)r * HD_ + col);
            }
            cp_commit();
        }

        // ---- S = Q . K^T ----
        const __nv_bfloat16* Kp = Ks + cur * TILE_E;
        float s[16][4];
#pragma unroll
        for (int j = 0; j < 16; j++)
#pragma unroll
            for (int k = 0; k < 4; k++) s[j][k] = 0.f;
#pragma unroll
        for (int kk = 0; kk < 4; kk++) {
#pragma unroll
            for (int jp = 0; jp < 8; jp++) {
                uint32_t b0, b1, b2, b3;
                ldsm_x4(b0, b1, b2, b3,
                        smem_u32(Kp + (jp * 16 + lrow) * PITCH + kk * 16 + lcol));
                mma_bf16(s[2 * jp],     qA[kk][0], qA[kk][1], qA[kk][2], qA[kk][3], b0, b2);
                mma_bf16(s[2 * jp + 1], qA[kk][0], qA[kk][1], qA[kk][2], qA[kk][3], b1, b3);
            }
        }

        // ---- bias + mask; tile row max ----
        float mxa = -1e30f, mxb = -1e30f;
        const size_t coff = (size_t)kt * 128;
#pragma unroll
        for (int j = 0; j < 16; j++) {
            int n = j * 8 + tig * 2;
            float2 bA = *(const float2*)&biasA[coff + n];
            float2 bB = *(const float2*)&biasB[coff + n];
            float m0 = smaskf[coff + n], m1 = smaskf[coff + n + 1];
            s[j][0] += bA.x + m0;
            s[j][1] += bA.y + m1;
            s[j][2] += bB.x + m0;
            s[j][3] += bB.y + m1;
            mxa = fmaxf(mxa, fmaxf(s[j][0], s[j][1]));
            mxb = fmaxf(mxb, fmaxf(s[j][2], s[j][3]));
        }
        mxa = fmaxf(mxa, __shfl_xor_sync(0xffffffffu, mxa, 1));
        mxa = fmaxf(mxa, __shfl_xor_sync(0xffffffffu, mxa, 2));
        mxb = fmaxf(mxb, __shfl_xor_sync(0xffffffffu, mxb, 1));
        mxb = fmaxf(mxb, __shfl_xor_sync(0xffffffffu, mxb, 2));

        float mna = fmaxf(m_a, mxa), mnb = fmaxf(m_b, mxb);
        float sca = __expf(m_a - mna), scb = __expf(m_b - mnb);
        m_a = mna; m_b = mnb;

        float suma = 0.f, sumb = 0.f;
#pragma unroll
        for (int j = 0; j < 16; j++) {
            s[j][0] = __expf(s[j][0] - m_a);
            s[j][1] = __expf(s[j][1] - m_a);
            s[j][2] = __expf(s[j][2] - m_b);
            s[j][3] = __expf(s[j][3] - m_b);
            suma += s[j][0] + s[j][1];
            sumb += s[j][2] + s[j][3];
        }
        l_a = l_a * sca + suma;
        l_b = l_b * scb + sumb;
#pragma unroll
        for (int jj = 0; jj < 8; jj++) {
            cacc[jj][0] *= sca; cacc[jj][1] *= sca;
            cacc[jj][2] *= scb; cacc[jj][3] *= scb;
        }

        // ---- ctx += P . V ----
        const __nv_bfloat16* Vp = Vs + cur * TILE_E;
#pragma unroll
        for (int jc = 0; jc < 8; jc++) {
            uint32_t a0 = packbf(s[2 * jc][0],     s[2 * jc][1]);
            uint32_t a1 = packbf(s[2 * jc][2],     s[2 * jc][3]);
            uint32_t a2 = packbf(s[2 * jc + 1][0], s[2 * jc + 1][1]);
            uint32_t a3 = packbf(s[2 * jc + 1][2], s[2 * jc + 1][3]);
#pragma unroll
            for (int dp = 0; dp < 4; dp++) {
                uint32_t v0, v1, v2, v3;
                ldsm_x4_t(v0, v1, v2, v3,
                          smem_u32(Vp + (jc * 16 + lrow) * PITCH + dp * 16 + lcol));
                mma_bf16(cacc[2 * dp],     a0, a1, a2, a3, v0, v1);
                mma_bf16(cacc[2 * dp + 1], a0, a1, a2, a3, v2, v3);
            }
        }
    }

    l_a += __shfl_xor_sync(0xffffffffu, l_a, 1);
    l_a += __shfl_xor_sync(0xffffffffu, l_a, 2);
    l_b += __shfl_xor_sync(0xffffffffu, l_b, 1);
    l_b += __shfl_xor_sync(0xffffffffu, l_b, 2);
    float inva = 1.0f / l_a, invb = 1.0f / l_b;

    const size_t obase_a = (((size_t)b * S_ + ra) * NH_ + h) * HD_;
    const size_t obase_b = (((size_t)b * S_ + ra + 8) * NH_ + h) * HD_;
#pragma unroll
    for (int jj = 0; jj < 8; jj++) {
        int d = jj * 8 + tig * 2;
        *(__nv_bfloat162*)&g_ctx[obase_a + d] =
            __floats2bfloat162_rn(cacc[jj][0] * inva, cacc[jj][1] * inva);
        *(__nv_bfloat162*)&g_ctx[obase_b + d] =
            __floats2bfloat162_rn(cacc[jj][2] * invb, cacc[jj][3] * invb);
    }
}

// =================================================================
// K3: out projection + bias + residual (bf16). M=8192, N=1024, K=1024
// =================================================================
__global__ void __launch_bounds__(256) outproj_kernel(
    const float* __restrict__ b_out, const float* __restrict__ X)
{
    __shared__ __align__(16) __nv_bfloat16 As[2][128 * GP];
    __shared__ __align__(16) __nv_bfloat16 Bs[2][128 * GP];
    const int bm = blockIdx.y * 128, bn = blockIdx.x * 128;
    const int tid = threadIdx.x, wid = tid >> 5, lane = tid & 31;
    const int gid = lane >> 2, tig = lane & 3;
    const int lrow = lane & 15, lcol = (lane >> 4) << 3;
    const int warp_m = wid >> 2, warp_n = wid & 3;

    float acc[4][4][4];
#pragma unroll
    for (int i = 0; i < 4; i++)
#pragma unroll
        for (int j = 0; j < 4; j++)
#pragma unroll
            for (int k = 0; k < 4; k++) acc[i][j][k] = 0.f;

    const __nv_bfloat16* Abase = g_ctx + (size_t)bm * HID_;
    const __nv_bfloat16* Bbase = g_woutb + (size_t)bn * HID_;

    cpa_bf128x32(As[0], Abase, HID_);
    cpa_bf128x32(Bs[0], Bbase, HID_);
    cp_commit();

    const int NC = HID_ / 32;
    for (int c = 0; c < NC; c++) {
        int cur = c & 1;
        if (c + 1 < NC) {
            cpa_bf128x32(As[cur ^ 1], Abase + (c + 1) * 32, HID_);
            cpa_bf128x32(Bs[cur ^ 1], Bbase + (c + 1) * 32, HID_);
            cp_commit();
            cp_wait<1>();
        } else {
            cp_wait<0>();
        }
        __syncthreads();
        mma_block_bf16(As[cur], Bs[cur], warp_m, warp_n, lrow, lcol, acc);
        __syncthreads();
    }

#pragma unroll
    for (int i = 0; i < 4; i++) {
        int r0 = bm + warp_m * 64 + i * 16 + gid;
#pragma unroll
        for (int j = 0; j < 4; j++) {
            int n = bn + warp_n * 32 + j * 8 + tig * 2;
            float2 x0 = *(const float2*)&X[(size_t)r0 * HID_ + n];
            float2 x1 = *(const float2*)&X[(size_t)(r0 + 8) * HID_ + n];
            float b0 = b_out[n], b1 = b_out[n + 1];
            *(float2*)&g_h[(size_t)r0 * HID_ + n] =
                make_float2(acc[i][j][0] + b0 + x0.x, acc[i][j][1] + b1 + x0.y);
            *(float2*)&g_h[(size_t)(r0 + 8) * HID_ + n] =
                make_float2(acc[i][j][2] + b0 + x1.x, acc[i][j][3] + b1 + x1.y);
        }
    }
}

// =================================================================
// K4: LayerNorm per row of g_h -> d_out
// =================================================================
__global__ void __launch_bounds__(256) layernorm_kernel(
    const float* __restrict__ gamma, const float* __restrict__ beta,
    float* __restrict__ out)
{
    const size_t row = blockIdx.x;
    const float* hp = g_h + row * HID_;
    const int tid = threadIdx.x;
    const int n = tid * 4;

    float4 v = *(const float4*)(hp + n);
    __shared__ float red[256];

    red[tid] = v.x + v.y + v.z + v.w;
    __syncthreads();
    for (int s = 128; s > 0; s >>= 1) {
        if (tid < s) red[tid] += red[tid + s];
        __syncthreads();
    }
    float mean = red[0] * (1.0f / HID_);
    __syncthreads();

    float dx = v.x - mean, dy = v.y - mean, dz = v.z - mean, dw = v.w - mean;
    red[tid] = dx * dx + dy * dy + dz * dz + dw * dw;
    __syncthreads();
    for (int s = 128; s > 0; s >>= 1) {
        if (tid < s) red[tid] += red[tid + s];
        __syncthreads();
    }
    float inv = rsqrtf(red[0] * (1.0f / HID_) + 1e-12f);

    float4 o;
    o.x = dx * inv * gamma[n + 0] + beta[n + 0];
    o.y = dy * inv * gamma[n + 1] + beta[n + 1];
    o.z = dz * inv * gamma[n + 2] + beta[n + 2];
    o.w = dw * inv * gamma[n + 3] + beta[n + 3];
    *(float4*)(out + row * HID_ + n) = o;
}

// =================================================================
extern "C" void kernel_launch(void* const* d_in, const int* in_sizes, int n_in,
                              void* d_out, int out_size)
{
    const float*         x       = (const float*)d_in[0];
    const unsigned char* mask    = (const unsigned char*)d_in[1];
    const float*         rel_pos = (const float*)d_in[2];
    const float*         rel2d   = (const float*)d_in[3];
    const float*         w_qkv   = (const float*)d_in[4];
    const float*         q_bias  = (const float*)d_in[5];
    const float*         v_bias  = (const float*)d_in[6];
    const float*         w_out   = (const float*)d_in[7];
    const float*         b_out   = (const float*)d_in[8];
    const float*         gamma   = (const float*)d_in[9];
    const float*         beta    = (const float*)d_in[10];
    float*               out     = (float*)d_out;

    cudaFuncSetAttribute(fused_attn_kernel,
                         cudaFuncAttributeMaxDynamicSharedMemorySize, FUSED_SMEM);

    // converts (device globals written from device code only)
    f2bf_x_kernel<<<(B_ * S_ * HID_ / 4) / 256, 256>>>((const float4*)x);
    f2bf_wqkv_kernel<<<(3 * HID_ * HID_ / 4) / 256, 256>>>((const float4*)w_qkv);
    f2bf_wout_kernel<<<(HID_ * HID_ / 4) / 256, 256>>>((const float4*)w_out);
    relsum_kernel<<<(NH_ * S_ * S_ / 4) / 256, 256>>>(
        (const float4*)rel_pos, (const float4*)rel2d);

    qkv_gemm_kernel<<<dim3(24, 64), 256>>>(q_bias, v_bias);
    fused_attn_kernel<<<dim3(B_, 8, NH_), 256, FUSED_SMEM>>>(mask);
    outproj_kernel<<<dim3(8, 64), 256>>>(b_out, x);
    layernorm_kernel<<<dim3(B_ * S_), 256>>>(gamma, beta, out);
}

// round 12
// speedup vs baseline: 1.7240x; 1.0008x over previous
#include <cuda_runtime.h>
#include <cuda_bf16.h>
#include <cstdint>

#define B_   8
#define S_   1024
#define HID_ 1024
#define NH_  16
#define HD_  64

// ---------------- scratch (no allocations allowed) ----------------
__device__ __align__(16) __nv_bfloat16 g_q[B_ * NH_ * S_ * HD_];   // pre-scaled 1/8, +q_bias
__device__ __align__(16) __nv_bfloat16 g_k[B_ * NH_ * S_ * HD_];
__device__ __align__(16) __nv_bfloat16 g_v[B_ * NH_ * S_ * HD_];
__device__ __align__(16) float g_bias[(size_t)NH_ * S_ * S_];      // rel_pos + rel_2d
__device__ __align__(16) __nv_bfloat16 g_ctx[B_ * S_ * HID_];      // [b,s,h,d] bf16
__device__ __align__(16) float g_h[B_ * S_ * HID_];
__device__ __align__(16) __nv_bfloat16 g_xb[B_ * S_ * HID_];       // x in bf16
__device__ __align__(16) __nv_bfloat16 g_wqkvb[3 * HID_ * HID_];   // w_qkv bf16
__device__ __align__(16) __nv_bfloat16 g_woutb[HID_ * HID_];       // w_out bf16

// ---------------- helpers ----------------
__device__ __forceinline__ uint32_t smem_u32(const void* p) {
    return (uint32_t)__cvta_generic_to_shared(p);
}
__device__ __forceinline__ void cp16(uint32_t s, const void* g) {
    asm volatile("cp.async.cg.shared.global [%0], [%1], 16;\n" :: "r"(s), "l"(g));
}
__device__ __forceinline__ void cp_commit() { asm volatile("cp.async.commit_group;\n"); }
template<int N> __device__ __forceinline__ void cp_wait() {
    asm volatile("cp.async.wait_group %0;\n" :: "n"(N));
}
__device__ __forceinline__ void mma_bf16(float c[4],
    uint32_t a0, uint32_t a1, uint32_t a2, uint32_t a3, uint32_t b0, uint32_t b1)
{
    asm volatile(
        "mma.sync.aligned.m16n8k16.row.col.f32.bf16.bf16.f32 "
        "{%0,%1,%2,%3},{%4,%5,%6,%7},{%8,%9},{%0,%1,%2,%3};\n"
        : "+f"(c[0]), "+f"(c[1]), "+f"(c[2]), "+f"(c[3])
        : "r"(a0), "r"(a1), "r"(a2), "r"(a3), "r"(b0), "r"(b1));
}
__device__ __forceinline__ void ldsm_x4(uint32_t& r0, uint32_t& r1,
                                        uint32_t& r2, uint32_t& r3, uint32_t a)
{
    asm volatile("ldmatrix.sync.aligned.m8n8.x4.shared.b16 {%0,%1,%2,%3}, [%4];\n"
                 : "=r"(r0), "=r"(r1), "=r"(r2), "=r"(r3) : "r"(a));
}
__device__ __forceinline__ void ldsm_x4_t(uint32_t& r0, uint32_t& r1,
                                          uint32_t& r2, uint32_t& r3, uint32_t a)
{
    asm volatile("ldmatrix.sync.aligned.m8n8.x4.trans.shared.b16 {%0,%1,%2,%3}, [%4];\n"
                 : "=r"(r0), "=r"(r1), "=r"(r2), "=r"(r3) : "r"(a));
}
__device__ __forceinline__ uint32_t packbf(float x, float y) {
    __nv_bfloat162 t = __floats2bfloat162_rn(x, y);
    return *(uint32_t*)&t;
}

// =================================================================
// converts: fp32 -> bf16 into device globals (referenced from DEVICE code)
// =================================================================
__global__ void __launch_bounds__(256) f2bf_x_kernel(const float4* __restrict__ src) {
    size_t i = (size_t)blockIdx.x * 256 + threadIdx.x;
    float4 v = src[i];
    __nv_bfloat162* dst = (__nv_bfloat162*)g_xb;
    dst[2 * i]     = __floats2bfloat162_rn(v.x, v.y);
    dst[2 * i + 1] = __floats2bfloat162_rn(v.z, v.w);
}
__global__ void __launch_bounds__(256) f2bf_wqkv_kernel(const float4* __restrict__ src) {
    size_t i = (size_t)blockIdx.x * 256 + threadIdx.x;
    float4 v = src[i];
    __nv_bfloat162* dst = (__nv_bfloat162*)g_wqkvb;
    dst[2 * i]     = __floats2bfloat162_rn(v.x, v.y);
    dst[2 * i + 1] = __floats2bfloat162_rn(v.z, v.w);
}
__global__ void __launch_bounds__(256) f2bf_wout_kernel(const float4* __restrict__ src) {
    size_t i = (size_t)blockIdx.x * 256 + threadIdx.x;
    float4 v = src[i];
    __nv_bfloat162* dst = (__nv_bfloat162*)g_woutb;
    dst[2 * i]     = __floats2bfloat162_rn(v.x, v.y);
    dst[2 * i + 1] = __floats2bfloat162_rn(v.z, v.w);
}

// =================================================================
// K0: relsum = rel_pos + rel_2d
// =================================================================
__global__ void __launch_bounds__(256) relsum_kernel(
    const float4* __restrict__ a, const float4* __restrict__ b)
{
    size_t i = (size_t)blockIdx.x * 256 + threadIdx.x;
    float4 x = a[i], y = b[i];
    x.x += y.x; x.y += y.y; x.z += y.z; x.w += y.w;
    ((float4*)g_bias)[i] = x;
}

// ---------------- bf16 GEMM building blocks (BK=32, pitch 40) ----------------
#define GP 40
__device__ __forceinline__ void cpa_bf128x32(__nv_bfloat16* dst,
                                             const __nv_bfloat16* src, int ld)
{
    const int tid = threadIdx.x;
#pragma unroll
    for (int i = 0; i < 2; i++) {
        int idx = tid + i * 256;
        int r = idx >> 2, c = (idx & 3) * 8;
        cp16(smem_u32(dst + r * GP + c), src + (size_t)r * ld + c);
    }
}

__device__ __forceinline__ void mma_block_bf16(
    const __nv_bfloat16* As, const __nv_bfloat16* Bs,
    int warp_m, int warp_n, int lrow, int lcol, float acc[4][4][4])
{
#pragma unroll
    for (int ks = 0; ks < 2; ks++) {
        uint32_t a[4][4], bfr[2][4];
#pragma unroll
        for (int i = 0; i < 4; i++)
            ldsm_x4(a[i][0], a[i][1], a[i][2], a[i][3],
                    smem_u32(As + (warp_m * 64 + i * 16 + lrow) * GP + ks * 16 + lcol));
#pragma unroll
        for (int g = 0; g < 2; g++)
            ldsm_x4(bfr[g][0], bfr[g][1], bfr[g][2], bfr[g][3],
                    smem_u32(Bs + (warp_n * 32 + g * 16 + lrow) * GP + ks * 16 + lcol));
#pragma unroll
        for (int i = 0; i < 4; i++)
#pragma unroll
            for (int g = 0; g < 2; g++) {
                mma_bf16(acc[i][2 * g],     a[i][0], a[i][1], a[i][2], a[i][3],
                         bfr[g][0], bfr[g][2]);
                mma_bf16(acc[i][2 * g + 1], a[i][0], a[i][1], a[i][2], a[i][3],
                         bfr[g][1], bfr[g][3]);
            }
    }
}

// =================================================================
// K1: QKV projection (bf16). M=8192, N=3072, K=1024
// =================================================================
__device__ __forceinline__ void qkv_store(int bb, int ss, int n, float2 v,
                                          const float* qb, const float* vb)
{
    if (n < HID_) {
        int h = n >> 6, d = n & 63;
        *(__nv_bfloat162*)&g_q[(((size_t)(bb * NH_ + h)) * S_ + ss) * HD_ + d] =
            __floats2bfloat162_rn((v.x + qb[n]) * 0.125f, (v.y + qb[n + 1]) * 0.125f);
    } else if (n < 2 * HID_) {
        int nn = n - HID_;
        int h = nn >> 6, d = nn & 63;
        *(__nv_bfloat162*)&g_k[(((size_t)(bb * NH_ + h)) * S_ + ss) * HD_ + d] =
            __floats2bfloat162_rn(v.x, v.y);
    } else {
        int nn = n - 2 * HID_;
        int h = nn >> 6, d = nn & 63;
        *(__nv_bfloat162*)&g_v[(((size_t)(bb * NH_ + h)) * S_ + ss) * HD_ + d] =
            __floats2bfloat162_rn(v.x + vb[nn], v.y + vb[nn + 1]);
    }
}

__global__ void __launch_bounds__(256) qkv_gemm_kernel(
    const float* __restrict__ qb, const float* __restrict__ vb)
{
    __shared__ __align__(16) __nv_bfloat16 As[2][128 * GP];
    __shared__ __align__(16) __nv_bfloat16 Bs[2][128 * GP];
    const int bm = blockIdx.y * 128, bn = blockIdx.x * 128;
    const int tid = threadIdx.x, wid = tid >> 5, lane = tid & 31;
    const int gid = lane >> 2, tig = lane & 3;
    const int lrow = lane & 15, lcol = (lane >> 4) << 3;
    const int warp_m = wid >> 2, warp_n = wid & 3;

    float acc[4][4][4];
#pragma unroll
    for (int i = 0; i < 4; i++)
#pragma unroll
        for (int j = 0; j < 4; j++)
#pragma unroll
            for (int k = 0; k < 4; k++) acc[i][j][k] = 0.f;

    const __nv_bfloat16* Abase = g_xb + (size_t)bm * HID_;
    const __nv_bfloat16* Bbase = g_wqkvb + (size_t)bn * HID_;

    cpa_bf128x32(As[0], Abase, HID_);
    cpa_bf128x32(Bs[0], Bbase, HID_);
    cp_commit();

    const int NC = HID_ / 32;
    for (int c = 0; c < NC; c++) {
        int cur = c & 1;
        if (c + 1 < NC) {
            cpa_bf128x32(As[cur ^ 1], Abase + (c + 1) * 32, HID_);
            cpa_bf128x32(Bs[cur ^ 1], Bbase + (c + 1) * 32, HID_);
            cp_commit();
            cp_wait<1>();
        } else {
            cp_wait<0>();
        }
        __syncthreads();
        mma_block_bf16(As[cur], Bs[cur], warp_m, warp_n, lrow, lcol, acc);
        __syncthreads();
    }

    const int bb = bm >> 10, ss0 = bm & 1023;
#pragma unroll
    for (int i = 0; i < 4; i++) {
        int r = warp_m * 64 + i * 16 + gid;
#pragma unroll
        for (int j = 0; j < 4; j++) {
            int n = bn + warp_n * 32 + j * 8 + tig * 2;
            qkv_store(bb, ss0 + r,     n, make_float2(acc[i][j][0], acc[i][j][1]), qb, vb);
            qkv_store(bb, ss0 + r + 8, n, make_float2(acc[i][j][2], acc[i][j][3]), qb, vb);
        }
    }
}

// =================================================================
// K2 (FUSED, bf16): flash attention with precomputed bias.
// =================================================================
#define PITCH 72
#define TILE_E (128 * PITCH)
#define FUSED_SMEM (5 * TILE_E * 2 + 1024 * 4)

extern __shared__ char dynsmem[];

__global__ void __launch_bounds__(256, 1) fused_attn_kernel(
    const unsigned char* __restrict__ mask)
{
    const int b  = blockIdx.x;
    const int qt = blockIdx.y;
    const int h  = blockIdx.z;
    const int bh = b * NH_ + h;

    __nv_bfloat16* Qs = (__nv_bfloat16*)dynsmem;          // [128][72]
    __nv_bfloat16* Ks = Qs + TILE_E;                      // 2 x [128][72]
    __nv_bfloat16* Vs = Ks + 2 * TILE_E;                  // 2 x [128][72]
    float* smaskf = (float*)(Vs + 2 * TILE_E);            // [1024]

    const int tid = threadIdx.x, wid = tid >> 5, lane = tid & 31;
    const int gid = lane >> 2, tig = lane & 3;

    const __nv_bfloat16* Qg = g_q + (size_t)bh * S_ * HD_ + (size_t)(qt * 128) * HD_;
    const __nv_bfloat16* Kg = g_k + (size_t)bh * S_ * HD_;
    const __nv_bfloat16* Vg = g_v + (size_t)bh * S_ * HD_;

    // prologue (128x64 bf16 tiles, 4 cp16/thread)
    {
#pragma unroll
        for (int i = 0; i < 4; i++) {
            int c = tid + i * 256;
            int r = c >> 3, col = (c & 7) * 8;
            cp16(smem_u32(Qs + r * PITCH + col), Qg + (size_t)r * HD_ + col);
        }
        cp_commit();
#pragma unroll
        for (int i = 0; i < 4; i++) {
            int c = tid + i * 256;
            int r = c >> 3, col = (c & 7) * 8;
            cp16(smem_u32(Ks + r * PITCH + col), Kg + (size_t)r * HD_ + col);
        }
#pragma unroll
        for (int i = 0; i < 4; i++) {
            int c = tid + i * 256;
            int r = c >> 3, col = (c & 7) * 8;
            cp16(smem_u32(Vs + r * PITCH + col), Vg + (size_t)r * HD_ + col);
        }
        cp_commit();
    }

    const unsigned char* mrow = mask + b * S_;
#pragma unroll
    for (int i = 0; i < 4; i++)
        smaskf[tid * 4 + i] = mrow[tid * 4 + i] ? -1e30f : 0.f;

    cp_wait<1>();        // Qs ready
    __syncthreads();

    const int lrow = lane & 15;
    const int lcol = (lane >> 4) << 3;

    uint32_t qA[4][4];
#pragma unroll
    for (int kk = 0; kk < 4; kk++)
        ldsm_x4(qA[kk][0], qA[kk][1], qA[kk][2], qA[kk][3],
                smem_u32(Qs + (wid * 16 + lrow) * PITCH + kk * 16 + lcol));

    float m_a = -1e30f, m_b = -1e30f;
    float l_a = 0.f,    l_b = 0.f;
    float cacc[8][4];
#pragma unroll
    for (int jj = 0; jj < 8; jj++)
#pragma unroll
        for (int k = 0; k < 4; k++) cacc[jj][k] = 0.f;

    const int r0 = wid * 16 + gid;
    const int ra = qt * 128 + r0;
    const float* biasA = g_bias + ((size_t)h * S_ + ra) * S_;
    const float* biasB = biasA + 8 * S_;

    for (int kt = 0; kt < 8; kt++) {
        const int cur = kt & 1;
        cp_wait<0>();
        __syncthreads();

        if (kt + 1 < 8) {
            const __nv_bfloat16* Kn = Kg + (size_t)(kt + 1) * 128 * HD_;
            const __nv_bfloat16* Vn = Vg + (size_t)(kt + 1) * 128 * HD_;
            __nv_bfloat16* Kd = Ks + (cur ^ 1) * TILE_E;
            __nv_bfloat16* Vd = Vs + (cur ^ 1) * TILE_E;
#pragma unroll
            for (int i = 0; i < 4; i++) {
                int c = tid + i * 256;
                int r = c >> 3, col = (c & 7) * 8;
                cp16(smem_u32(Kd + r * PITCH + col), Kn + (size_t)r * HD_ + col);
            }
#pragma unroll
            for (int i = 0; i < 4; i++) {
                int c = tid + i * 256;
                int r = c >> 3, col = (c & 7) * 8;
                cp16(smem_u32(Vd + r * PITCH + col), Vn + (size_t)r * HD_ + col);
            }
            cp_commit();
        }

        // ---- S = Q . K^T ----
        const __nv_bfloat16* Kp = Ks + cur * TILE_E;
        float s[16][4];
#pragma unroll
        for (int j = 0; j < 16; j++)
#pragma unroll
            for (int k = 0; k < 4; k++) s[j][k] = 0.f;
#pragma unroll
        for (int kk = 0; kk < 4; kk++) {
#pragma unroll
            for (int jp = 0; jp < 8; jp++) {
                uint32_t b0, b1, b2, b3;
                ldsm_x4(b0, b1, b2, b3,
                        smem_u32(Kp + (jp * 16 + lrow) * PITCH + kk * 16 + lcol));
                mma_bf16(s[2 * jp],     qA[kk][0], qA[kk][1], qA[kk][2], qA[kk][3], b0, b2);
                mma_bf16(s[2 * jp + 1], qA[kk][0], qA[kk][1], qA[kk][2], qA[kk][3], b1, b3);
            }
        }

        // ---- bias + mask; tile row max ----
        float mxa = -1e30f, mxb = -1e30f;
        const size_t coff = (size_t)kt * 128;
#pragma unroll
        for (int j = 0; j < 16; j++) {
            int n = j * 8 + tig * 2;
            float2 bA = *(const float2*)&biasA[coff + n];
            float2 bB = *(const float2*)&biasB[coff + n];
            float m0 = smaskf[coff + n], m1 = smaskf[coff + n + 1];
            s[j][0] += bA.x + m0;
            s[j][1] += bA.y + m1;
            s[j][2] += bB.x + m0;
            s[j][3] += bB.y + m1;
            mxa = fmaxf(mxa, fmaxf(s[j][0], s[j][1]));
            mxb = fmaxf(mxb, fmaxf(s[j][2], s[j][3]));
        }
        mxa = fmaxf(mxa, __shfl_xor_sync(0xffffffffu, mxa, 1));
        mxa = fmaxf(mxa, __shfl_xor_sync(0xffffffffu, mxa, 2));
        mxb = fmaxf(mxb, __shfl_xor_sync(0xffffffffu, mxb, 1));
        mxb = fmaxf(mxb, __shfl_xor_sync(0xffffffffu, mxb, 2));

        float mna = fmaxf(m_a, mxa), mnb = fmaxf(m_b, mxb);
        float sca = __expf(m_a - mna), scb = __expf(m_b - mnb);
        m_a = mna; m_b = mnb;

        float suma = 0.f, sumb = 0.f;
#pragma unroll
        for (int j = 0; j < 16; j++) {
            s[j][0] = __expf(s[j][0] - m_a);
            s[j][1] = __expf(s[j][1] - m_a);
            s[j][2] = __expf(s[j][2] - m_b);
            s[j][3] = __expf(s[j][3] - m_b);
            suma += s[j][0] + s[j][1];
            sumb += s[j][2] + s[j][3];
        }
        l_a = l_a * sca + suma;
        l_b = l_b * scb + sumb;
#pragma unroll
        for (int jj = 0; jj < 8; jj++) {
            cacc[jj][0] *= sca; cacc[jj][1] *= sca;
            cacc[jj][2] *= scb; cacc[jj][3] *= scb;
        }

        // ---- ctx += P . V ----
        const __nv_bfloat16* Vp = Vs + cur * TILE_E;
#pragma unroll
        for (int jc = 0; jc < 8; jc++) {
            uint32_t a0 = packbf(s[2 * jc][0],     s[2 * jc][1]);
            uint32_t a1 = packbf(s[2 * jc][2],     s[2 * jc][3]);
            uint32_t a2 = packbf(s[2 * jc + 1][0], s[2 * jc + 1][1]);
            uint32_t a3 = packbf(s[2 * jc + 1][2], s[2 * jc + 1][3]);
#pragma unroll
            for (int dp = 0; dp < 4; dp++) {
                uint32_t v0, v1, v2, v3;
                ldsm_x4_t(v0, v1, v2, v3,
                          smem_u32(Vp + (jc * 16 + lrow) * PITCH + dp * 16 + lcol));
                mma_bf16(cacc[2 * dp],     a0, a1, a2, a3, v0, v1);
                mma_bf16(cacc[2 * dp + 1], a0, a1, a2, a3, v2, v3);
            }
        }
    }

    l_a += __shfl_xor_sync(0xffffffffu, l_a, 1);
    l_a += __shfl_xor_sync(0xffffffffu, l_a, 2);
    l_b += __shfl_xor_sync(0xffffffffu, l_b, 1);
    l_b += __shfl_xor_sync(0xffffffffu, l_b, 2);
    float inva = 1.0f / l_a, invb = 1.0f / l_b;

    const size_t obase_a = (((size_t)b * S_ + ra) * NH_ + h) * HD_;
    const size_t obase_b = (((size_t)b * S_ + ra + 8) * NH_ + h) * HD_;
#pragma unroll
    for (int jj = 0; jj < 8; jj++) {
        int d = jj * 8 + tig * 2;
        *(__nv_bfloat162*)&g_ctx[obase_a + d] =
            __floats2bfloat162_rn(cacc[jj][0] * inva, cacc[jj][1] * inva);
        *(__nv_bfloat162*)&g_ctx[obase_b + d] =
            __floats2bfloat162_rn(cacc[jj][2] * invb, cacc[jj][3] * invb);
    }
}

// =================================================================
// K3: out projection + bias + residual (bf16). M=8192, N=1024, K=1024
// =================================================================
__global__ void __launch_bounds__(256) outproj_kernel(
    const float* __restrict__ b_out, const float* __restrict__ X)
{
    __shared__ __align__(16) __nv_bfloat16 As[2][128 * GP];
    __shared__ __align__(16) __nv_bfloat16 Bs[2][128 * GP];
    const int bm = blockIdx.y * 128, bn = blockIdx.x * 128;
    const int tid = threadIdx.x, wid = tid >> 5, lane = tid & 31;
    const int gid = lane >> 2, tig = lane & 3;
    const int lrow = lane & 15, lcol = (lane >> 4) << 3;
    const int warp_m = wid >> 2, warp_n = wid & 3;

    float acc[4][4][4];
#pragma unroll
    for (int i = 0; i < 4; i++)
#pragma unroll
        for (int j = 0; j < 4; j++)
#pragma unroll
            for (int k = 0; k < 4; k++) acc[i][j][k] = 0.f;

    const __nv_bfloat16* Abase = g_ctx + (size_t)bm * HID_;
    const __nv_bfloat16* Bbase = g_woutb + (size_t)bn * HID_;

    cpa_bf128x32(As[0], Abase, HID_);
    cpa_bf128x32(Bs[0], Bbase, HID_);
    cp_commit();

    const int NC = HID_ / 32;
    for (int c = 0; c < NC; c++) {
        int cur = c & 1;
        if (c + 1 < NC) {
            cpa_bf128x32(As[cur ^ 1], Abase + (c + 1) * 32, HID_);
            cpa_bf128x32(Bs[cur ^ 1], Bbase + (c + 1) * 32, HID_);
            cp_commit();
            cp_wait<1>();
        } else {
            cp_wait<0>();
        }
        __syncthreads();
        mma_block_bf16(As[cur], Bs[cur], warp_m, warp_n, lrow, lcol, acc);
        __syncthreads();
    }

#pragma unroll
    for (int i = 0; i < 4; i++) {
        int r0 = bm + warp_m * 64 + i * 16 + gid;
#pragma unroll
        for (int j = 0; j < 4; j++) {
            int n = bn + warp_n * 32 + j * 8 + tig * 2;
            float2 x0 = *(const float2*)&X[(size_t)r0 * HID_ + n];
            float2 x1 = *(const float2*)&X[(size_t)(r0 + 8) * HID_ + n];
            float b0 = b_out[n], b1 = b_out[n + 1];
            *(float2*)&g_h[(size_t)r0 * HID_ + n] =
                make_float2(acc[i][j][0] + b0 + x0.x, acc[i][j][1] + b1 + x0.y);
            *(float2*)&g_h[(size_t)(r0 + 8) * HID_ + n] =
                make_float2(acc[i][j][2] + b0 + x1.x, acc[i][j][3] + b1 + x1.y);
        }
    }
}

// =================================================================
// K4: LayerNorm per row of g_h -> d_out
// =================================================================
__global__ void __launch_bounds__(256) layernorm_kernel(
    const float* __restrict__ gamma, const float* __restrict__ beta,
    float* __restrict__ out)
{
    const size_t row = blockIdx.x;
    const float* hp = g_h + row * HID_;
    const int tid = threadIdx.x;
    const int n = tid * 4;

    float4 v = *(const float4*)(hp + n);
    __shared__ float red[256];

    red[tid] = v.x + v.y + v.z + v.w;
    __syncthreads();
    for (int s = 128; s > 0; s >>= 1) {
        if (tid < s) red[tid] += red[tid + s];
        __syncthreads();
    }
    float mean = red[0] * (1.0f / HID_);
    __syncthreads();

    float dx = v.x - mean, dy = v.y - mean, dz = v.z - mean, dw = v.w - mean;
    red[tid] = dx * dx + dy * dy + dz * dz + dw * dw;
    __syncthreads();
    for (int s = 128; s > 0; s >>= 1) {
        if (tid < s) red[tid] += red[tid + s];
        __syncthreads();
    }
    float inv = rsqrtf(red[0] * (1.0f / HID_) + 1e-12f);

    float4 o;
    o.x = dx * inv * gamma[n + 0] + beta[n + 0];
    o.y = dy * inv * gamma[n + 1] + beta[n + 1];
    o.z = dz * inv * gamma[n + 2] + beta[n + 2];
    o.w = dw * inv * gamma[n + 3] + beta[n + 3];
    *(float4*)(out + row * HID_ + n) = o;
}

// =================================================================
extern "C" void kernel_launch(void* const* d_in, const int* in_sizes, int n_in,
                              void* d_out, int out_size)
{
    const float*         x       = (const float*)d_in[0];
    const unsigned char* mask    = (const unsigned char*)d_in[1];
    const float*         rel_pos = (const float*)d_in[2];
    const float*         rel2d   = (const float*)d_in[3];
    const float*         w_qkv   = (const float*)d_in[4];
    const float*         q_bias  = (const float*)d_in[5];
    const float*         v_bias  = (const float*)d_in[6];
    const float*         w_out   = (const float*)d_in[7];
    const float*         b_out   = (const float*)d_in[8];
    const float*         gamma   = (const float*)d_in[9];
    const float*         beta    = (const float*)d_in[10];
    float*               out     = (float*)d_out;

    cudaFuncSetAttribute(fused_attn_kernel,
                         cudaFuncAttributeMaxDynamicSharedMemorySize, FUSED_SMEM);

    // converts (device globals written from device code only)
    f2bf_x_kernel<<<(B_ * S_ * HID_ / 4) / 256, 256>>>((const float4*)x);
    f2bf_wqkv_kernel<<<(3 * HID_ * HID_ / 4) / 256, 256>>>((const float4*)w_qkv);
    f2bf_wout_kernel<<<(HID_ * HID_ / 4) / 256, 256>>>((const float4*)w_out);
    relsum_kernel<<<(NH_ * S_ * S_ / 4) / 256, 256>>>(
        (const float4*)rel_pos, (const float4*)rel2d);

    qkv_gemm_kernel<<<dim3(24, 64), 256>>>(q_bias, v_bias);
    fused_attn_kernel<<<dim3(B_, 8, NH_), 256, FUSED_SMEM>>>(mask);
    outproj_kernel<<<dim3(8, 64), 256>>>(b_out, x);
    layernorm_kernel<<<dim3(B_ * S_), 256>>>(gamma, beta, out);
}